// round 3
// baseline (speedup 1.0000x reference)
#include <cuda_runtime.h>
#include <cstdint>

// Problem constants
#define BB   128      // batch
#define TT   1024     // timesteps
#define HH   512      // hidden
#define VV   256      // vocab
#define NCTA 128      // persistent CTAs (one wave guaranteed; 148 SMs)
#define NTHR 256

// ---------------------------------------------------------------------------
// Device scratch (static __device__ arrays: allocation-free per harness rules)
// ---------------------------------------------------------------------------
__device__ float g_h1[2][HH * BB];          // double-buffered, layout [j][b]
__device__ float g_h2[HH * BB];             // single buffer,   layout [j][b]
__device__ float g_xT[TT * BB];             // x transposed [t][b]
__device__ float g_WlinT[HH * VV];          // W_lin transposed [k][v]
__device__ float g_h2all[(size_t)TT * HH * BB];  // [t][j][b]  (256 MB)
__device__ unsigned g_barcnt;
__device__ unsigned g_bargen;

// ---------------------------------------------------------------------------
// Grid-wide barrier (all NCTA CTAs resident => no deadlock).
// ---------------------------------------------------------------------------
__device__ __forceinline__ void grid_barrier() {
    __threadfence();
    __syncthreads();
    if (threadIdx.x == 0) {
        unsigned gen = *(volatile unsigned*)&g_bargen;
        unsigned arrived = atomicAdd(&g_barcnt, 1u);
        if (arrived == NCTA - 1) {
            *(volatile unsigned*)&g_barcnt = 0u;
            __threadfence();
            atomicAdd(&g_bargen, 1u);
        } else {
            while (*(volatile unsigned*)&g_bargen == gen) { }
        }
    }
    __syncthreads();
    __threadfence();
}

__device__ __forceinline__ float sigf(float x) { return 1.0f / (1.0f + expf(-x)); }

// ---------------------------------------------------------------------------
// 16-output (4b x 4c) fp32 micro-tile GEMM over k in [k0, k1).
// A: [k][b] layout in GLOBAL (read .cg: cross-CTA producer, L1 not coherent)
// Ws: [k][16] layout in SMEM (CTA-resident weight slice)
// ---------------------------------------------------------------------------
__device__ __forceinline__ void gemm16(float acc[4][4],
                                       const float* __restrict__ A,
                                       const float* __restrict__ Ws,
                                       int b4, int c4, int k0, int k1) {
    const float4* __restrict__ ap = reinterpret_cast<const float4*>(A + b4);
    const float4* __restrict__ wp = reinterpret_cast<const float4*>(Ws + c4);
#pragma unroll 8
    for (int k = k0; k < k1; ++k) {
        float4 hv = __ldcg(ap + k * (BB / 4));
        float4 wv = wp[k * 4];
        float hb[4] = {hv.x, hv.y, hv.z, hv.w};
        float wc[4] = {wv.x, wv.y, wv.z, wv.w};
#pragma unroll
        for (int bi = 0; bi < 4; ++bi)
#pragma unroll
            for (int cj = 0; cj < 4; ++cj)
                acc[bi][cj] = fmaf(hb[bi], wc[cj], acc[bi][cj]);
    }
}

// ---------------------------------------------------------------------------
// Persistent recurrent kernel.
// CTA c owns hidden indices j in [4c, 4c+4) for BOTH layers.
// SMEM weight slices are gate-interleaved: col = gate*4 + jj, actual weight
// row = gate*HH + 4c + jj  (PyTorch gate order i,f,g,o).
// Stage 1: threads 0..127 run layer-1 GEMM (h1_prev) + layer-1 activation;
//          threads 128..255 run layer-2 hh-GEMM (accumulators persist).
// Stage 2 (after grid barrier): ih-GEMM K-split across BOTH halves
//          (lower: k in [0,256) -> SMEM partial; upper: k in [256,512) +
//          merge + layer-2 activation).
// ---------------------------------------------------------------------------
__global__ void __launch_bounds__(NTHR, 1)
lstm_persist(const float* __restrict__ x,
             const float* __restrict__ Wih1, const float* __restrict__ Whh1,
             const float* __restrict__ bih1, const float* __restrict__ bhh1,
             const float* __restrict__ Wih2, const float* __restrict__ Whh2,
             const float* __restrict__ bih2, const float* __restrict__ bhh2,
             const float* __restrict__ Wlin) {
    extern __shared__ float smem[];
    float* W1s   = smem;              // 512*16
    float* W2hs  = W1s  + 8192;       // 512*16
    float* W2is  = W2hs + 8192;       // 512*16
    float* gateA = W2is + 8192;       // 16*128 (stage1 gate xchg / stage2 partial)
    float* gateB = gateA + 2048;      // 16*128
    float* c1s   = gateB + 2048;      // 4*128
    float* c2s   = c1s + 512;         // 4*128
    float* bias1 = c2s + 512;         // 16
    float* wih1s = bias1 + 16;        // 16
    float* bias2 = wih1s + 16;        // 16

    const int cta = blockIdx.x;
    const int tid = threadIdx.x;

    // ---- Prologue: weight slices (gate-interleaved gather), biases, state ----
    for (int idx = tid; idx < 16 * HH; idx += NTHR) {
        int col = idx >> 9;           // 0..15
        int k   = idx & (HH - 1);     // 0..511 (consecutive -> coalesced LDG)
        int row = (col >> 2) * HH + cta * 4 + (col & 3);
        W1s [k * 16 + col] = Whh1[row * HH + k];
        W2hs[k * 16 + col] = Whh2[row * HH + k];
        W2is[k * 16 + col] = Wih2[row * HH + k];
    }
    if (tid < 16) {
        int col = tid;
        int row = (col >> 2) * HH + cta * 4 + (col & 3);
        bias1[col] = bih1[row] + bhh1[row];
        wih1s[col] = Wih1[row];       // W_ih1 is [4H, 1]
        bias2[col] = bih2[row] + bhh2[row];
    }
    for (int i = tid; i < 512; i += NTHR) { c1s[i] = 0.0f; c2s[i] = 0.0f; }

    // Grid-strided global init: zero h state, transpose x and W_lin.
    const int gtid = cta * NTHR + tid;
    const int gstr = NCTA * NTHR;
    for (int i = gtid; i < HH * BB; i += gstr) {
        g_h1[0][i] = 0.0f; g_h1[1][i] = 0.0f; g_h2[i] = 0.0f;
    }
    for (int i = gtid; i < TT * BB; i += gstr) {
        int t = i >> 7, b = i & (BB - 1);
        g_xT[i] = x[b * TT + t];
    }
    for (int i = gtid; i < HH * VV; i += gstr) {
        int k = i >> 8, v = i & (VV - 1);
        g_WlinT[i] = Wlin[v * HH + k];
    }
    __syncthreads();
    grid_barrier();

    // ---- Time loop ----
    const int lt = tid & 127;         // role-local thread id
    const int tb = lt >> 2;           // 0..31  (b-tile)
    const int tc = lt & 3;            // 0..3   (c-tile)
    for (int t = 0; t < TT; ++t) {
        const int hp = t & 1;
        float acc2[4][4];

        if (tid < 128) {
            // ---- layer 1: g1 = bias + x*Wih1 + h1_prev @ Whh1^T ----
            float acc[4][4];
            float4 xv = *(const float4*)&g_xT[t * BB + tb * 4];
            float xb[4] = {xv.x, xv.y, xv.z, xv.w};
#pragma unroll
            for (int bi = 0; bi < 4; ++bi)
#pragma unroll
                for (int cj = 0; cj < 4; ++cj)
                    acc[bi][cj] = bias1[tc * 4 + cj] + xb[bi] * wih1s[tc * 4 + cj];
            gemm16(acc, g_h1[hp], W1s, tb * 4, tc * 4, 0, HH);
            // exchange gates across the 4 gate-owning thread columns
#pragma unroll
            for (int cj = 0; cj < 4; ++cj)
                *(float4*)&gateA[(tc * 4 + cj) * BB + tb * 4] =
                    make_float4(acc[0][cj], acc[1][cj], acc[2][cj], acc[3][cj]);
            asm volatile("bar.sync 1, 128;" ::: "memory");
            // activation: thread owns batch row b = tid, jj = 0..3
            int b = tid;
#pragma unroll
            for (int jj = 0; jj < 4; ++jj) {
                float gi = gateA[(0  + jj) * BB + b];
                float gf = gateA[(4  + jj) * BB + b];
                float gg = gateA[(8  + jj) * BB + b];
                float go = gateA[(12 + jj) * BB + b];
                float c0 = c1s[jj * BB + b];
                float cn = sigf(gf) * c0 + sigf(gi) * tanhf(gg);
                c1s[jj * BB + b] = cn;
                g_h1[1 - hp][(cta * 4 + jj) * BB + b] = sigf(go) * tanhf(cn);
            }
        } else {
            // ---- layer 2, recurrent part: g2 = bias + h2_prev @ Whh2^T ----
#pragma unroll
            for (int bi = 0; bi < 4; ++bi)
#pragma unroll
                for (int cj = 0; cj < 4; ++cj)
                    acc2[bi][cj] = bias2[tc * 4 + cj];
            gemm16(acc2, g_h2, W2hs, tb * 4, tc * 4, 0, HH);
        }

        grid_barrier();   // h1_new visible everywhere; all h2_prev reads done
                          // (also orders gateA reuse below after activation reads)

        // ---- layer 2, input part (K-split across both halves) ----
        if (tid < 128) {
            // lower half: partial over k in [0, 256) -> SMEM
            float accp[4][4];
#pragma unroll
            for (int bi = 0; bi < 4; ++bi)
#pragma unroll
                for (int cj = 0; cj < 4; ++cj) accp[bi][cj] = 0.0f;
            gemm16(accp, g_h1[1 - hp], W2is, tb * 4, tc * 4, 0, HH / 2);
            // store tile transposed: [16][128], lane-contiguous (no conflicts)
#pragma unroll
            for (int bi = 0; bi < 4; ++bi)
#pragma unroll
                for (int cj = 0; cj < 4; ++cj)
                    gateA[(bi * 4 + cj) * 128 + lt] = accp[bi][cj];
        } else {
            // upper half: own partial over k in [256, 512)
            gemm16(acc2, g_h1[1 - hp], W2is, tb * 4, tc * 4, HH / 2, HH);
        }
        __syncthreads();

        if (tid >= 128) {
            // merge lower-half partial
#pragma unroll
            for (int bi = 0; bi < 4; ++bi)
#pragma unroll
                for (int cj = 0; cj < 4; ++cj)
                    acc2[bi][cj] += gateA[(bi * 4 + cj) * 128 + lt];
            // gate exchange
#pragma unroll
            for (int cj = 0; cj < 4; ++cj)
                *(float4*)&gateB[(tc * 4 + cj) * BB + tb * 4] =
                    make_float4(acc2[0][cj], acc2[1][cj], acc2[2][cj], acc2[3][cj]);
            asm volatile("bar.sync 2, 128;" ::: "memory");
            int b = lt;
#pragma unroll
            for (int jj = 0; jj < 4; ++jj) {
                float gi = gateB[(0  + jj) * BB + b];
                float gf = gateB[(4  + jj) * BB + b];
                float gg = gateB[(8  + jj) * BB + b];
                float go = gateB[(12 + jj) * BB + b];
                float c0 = c2s[jj * BB + b];
                float cn = sigf(gf) * c0 + sigf(gi) * tanhf(gg);
                c2s[jj * BB + b] = cn;
                float hn = sigf(go) * tanhf(cn);
                g_h2[(cta * 4 + jj) * BB + b] = hn;
                g_h2all[(size_t)t * (HH * BB) + (cta * 4 + jj) * BB + b] = hn;
            }
        }

        grid_barrier();   // h2_new visible everywhere; gateA free for next step
    }
}

// ---------------------------------------------------------------------------
// Final phase: logits = h2_all @ W_lin^T + b_lin, then softmax over V.
// grid = TT*4; CTA handles (t, 32-batch block), all 256 vocab columns.
// Thread (tb=warp, tc=lane): 4 batch rows x 8 vocab cols.
// ---------------------------------------------------------------------------
__global__ void __launch_bounds__(NTHR)
lin_softmax(const float* __restrict__ blin, float* __restrict__ out) {
    __shared__ float w_s[32 * VV];    // 32 k-rows x 256 v (32 KB)
    const int bx = blockIdx.x;
    const int t  = bx >> 2;
    const int bbk = bx & 3;           // 32-row batch block
    const int tid = threadIdx.x;
    const int tb = tid >> 5;          // warp id = batch sub-tile
    const int tc = tid & 31;          // lane = vocab sub-tile

    float acc[4][8];
#pragma unroll
    for (int i = 0; i < 4; ++i)
#pragma unroll
        for (int j = 0; j < 8; ++j) acc[i][j] = 0.0f;

    for (int k0 = 0; k0 < HH; k0 += 32) {
        __syncthreads();
        for (int i = tid; i < 32 * VV; i += NTHR)
            w_s[i] = g_WlinT[k0 * VV + i];
        __syncthreads();
#pragma unroll 8
        for (int kk = 0; kk < 32; ++kk) {
            float4 hv = *(const float4*)&g_h2all[(size_t)t * (HH * BB) +
                                                 (k0 + kk) * BB + bbk * 32 + tb * 4];
            float4 w0 = *(const float4*)&w_s[kk * VV + tc * 8];
            float4 w1 = *(const float4*)&w_s[kk * VV + tc * 8 + 4];
            float hb[4] = {hv.x, hv.y, hv.z, hv.w};
            float wc[8] = {w0.x, w0.y, w0.z, w0.w, w1.x, w1.y, w1.z, w1.w};
#pragma unroll
            for (int bi = 0; bi < 4; ++bi)
#pragma unroll
                for (int vj = 0; vj < 8; ++vj)
                    acc[bi][vj] = fmaf(hb[bi], wc[vj], acc[bi][vj]);
        }
    }

    float lb[8];
    *(float4*)&lb[0] = *(const float4*)&blin[tc * 8];
    *(float4*)&lb[4] = *(const float4*)&blin[tc * 8 + 4];

#pragma unroll
    for (int bi = 0; bi < 4; ++bi) {
        float m = -1e30f;
#pragma unroll
        for (int vj = 0; vj < 8; ++vj) {
            acc[bi][vj] += lb[vj];
            m = fmaxf(m, acc[bi][vj]);
        }
#pragma unroll
        for (int off = 16; off >= 1; off >>= 1)
            m = fmaxf(m, __shfl_xor_sync(0xffffffffu, m, off));
        float s = 0.0f;
#pragma unroll
        for (int vj = 0; vj < 8; ++vj) {
            float e = expf(acc[bi][vj] - m);
            acc[bi][vj] = e;
            s += e;
        }
#pragma unroll
        for (int off = 16; off >= 1; off >>= 1)
            s += __shfl_xor_sync(0xffffffffu, s, off);
        float inv = 1.0f / s;
        size_t b = (size_t)(bbk * 32 + tb * 4 + bi);
        float4 o0 = make_float4(acc[bi][0] * inv, acc[bi][1] * inv,
                                acc[bi][2] * inv, acc[bi][3] * inv);
        float4 o1 = make_float4(acc[bi][4] * inv, acc[bi][5] * inv,
                                acc[bi][6] * inv, acc[bi][7] * inv);
        float* op = out + b * ((size_t)TT * VV) + (size_t)t * VV + tc * 8;
        *(float4*)op       = o0;
        *(float4*)(op + 4) = o1;
    }
}

// ---------------------------------------------------------------------------
extern "C" void kernel_launch(void* const* d_in, const int* in_sizes, int n_in,
                              void* d_out, int out_size) {
    const float* x    = (const float*)d_in[0];
    const float* Wih1 = (const float*)d_in[1];
    const float* Whh1 = (const float*)d_in[2];
    const float* bih1 = (const float*)d_in[3];
    const float* bhh1 = (const float*)d_in[4];
    const float* Wih2 = (const float*)d_in[5];
    const float* Whh2 = (const float*)d_in[6];
    const float* bih2 = (const float*)d_in[7];
    const float* bhh2 = (const float*)d_in[8];
    const float* Wlin = (const float*)d_in[9];
    const float* blin = (const float*)d_in[10];

    const size_t smem_bytes = (3 * 8192 + 2 * 2048 + 2 * 512 + 48) * sizeof(float);
    cudaFuncSetAttribute(lstm_persist, cudaFuncAttributeMaxDynamicSharedMemorySize,
                         (int)smem_bytes);

    lstm_persist<<<NCTA, NTHR, smem_bytes>>>(x, Wih1, Whh1, bih1, bhh1,
                                             Wih2, Whh2, bih2, bhh2, Wlin);
    lin_softmax<<<TT * 4, NTHR>>>(blin, (float*)d_out);
}

// round 5
// speedup vs baseline: 2.0365x; 2.0365x over previous
#include <cuda_runtime.h>
#include <cuda_bf16.h>
#include <cstdint>

#define BB   128
#define TT   1024
#define HH   512
#define VV   256
#define NCTA 128
#define NTHR 256

// ---------------------------------------------------------------------------
// Device scratch (allocation-free per harness rules)
// h matrices: bf16 hi/lo pairs, layout [b][k]
// ---------------------------------------------------------------------------
__device__ __nv_bfloat16 g_h1hi[2][BB * HH];
__device__ __nv_bfloat16 g_h1lo[2][BB * HH];
__device__ __nv_bfloat16 g_h2hi[BB * HH];
__device__ __nv_bfloat16 g_h2lo[BB * HH];
__device__ float g_xT[TT * BB];                   // x transposed [t][b]
__device__ float g_WlinT[HH * VV];                // W_lin transposed [k][v]
__device__ float g_h2all[(size_t)TT * HH * BB];   // [t][j][b] fp32
__device__ unsigned g_barcnt, g_bargen;

// ---------------------------------------------------------------------------
// SMEM layout (bytes)
// A buffers: 2 x (hi 32KB + lo 32KB) = 128KB, rows 256B, XOR-16B swizzle
// W arrays : 6 x 16KB ([n=16][k=512] bf16, XOR-16B swizzle)  = 96KB
// ---------------------------------------------------------------------------
#define ABUF(b)   ((b) * 65536)
#define WOFF      131072
#define W1HI      (WOFF)
#define W1LO      (WOFF + 16384)
#define W2HHI     (WOFF + 32768)
#define W2HLO     (WOFF + 49152)
#define W2IHI     (WOFF + 65536)
#define W2ILO     (WOFF + 81920)
#define MISC      (WOFF + 98304)
#define SMEM_TOTAL (MISC + 256)

__device__ __forceinline__ uint32_t smem_u32(const void* p) {
    uint32_t a;
    asm("{ .reg .u64 t; cvta.to.shared.u64 t, %1; cvt.u32.u64 %0, t; }"
        : "=r"(a) : "l"(p));
    return a;
}
__device__ __forceinline__ float sigf(float x) { return 1.0f / (1.0f + expf(-x)); }

// ---------------------------------------------------------------------------
// Grid-wide barrier (128 resident CTAs; proven in R3)
// ---------------------------------------------------------------------------
__device__ __forceinline__ void grid_barrier() {
    __threadfence();
    __syncthreads();
    if (threadIdx.x == 0) {
        unsigned gen = *(volatile unsigned*)&g_bargen;
        unsigned arrived = atomicAdd(&g_barcnt, 1u);
        if (arrived == NCTA - 1) {
            *(volatile unsigned*)&g_barcnt = 0u;
            __threadfence();
            atomicAdd(&g_bargen, 1u);
        } else {
            while (*(volatile unsigned*)&g_bargen == gen) { }
        }
    }
    __syncthreads();
    __threadfence();
}

// ---------------------------------------------------------------------------
// HMMA / ldmatrix / cp.async primitives (all base-target-safe, sm_80+)
// ---------------------------------------------------------------------------
__device__ __forceinline__ void cpa16(uint32_t dst, const void* src) {
    asm volatile("cp.async.cg.shared.global [%0], [%1], 16;"
                 :: "r"(dst), "l"(src));
}
__device__ __forceinline__ void ldm4(uint32_t a[4], uint32_t addr) {
    asm volatile("ldmatrix.sync.aligned.m8n8.x4.shared.b16 {%0,%1,%2,%3}, [%4];"
                 : "=r"(a[0]), "=r"(a[1]), "=r"(a[2]), "=r"(a[3]) : "r"(addr));
}
__device__ __forceinline__ void ldm2(uint32_t b[2], uint32_t addr) {
    asm volatile("ldmatrix.sync.aligned.m8n8.x2.shared.b16 {%0,%1}, [%2];"
                 : "=r"(b[0]), "=r"(b[1]) : "r"(addr));
}
__device__ __forceinline__ void mma16816(float d[4], const uint32_t a[4],
                                         const uint32_t b[2]) {
    asm volatile(
        "mma.sync.aligned.m16n8k16.row.col.f32.bf16.bf16.f32 "
        "{%0,%1,%2,%3}, {%4,%5,%6,%7}, {%8,%9}, {%0,%1,%2,%3};"
        : "+f"(d[0]), "+f"(d[1]), "+f"(d[2]), "+f"(d[3])
        : "r"(a[0]), "r"(a[1]), "r"(a[2]), "r"(a[3]), "r"(b[0]), "r"(b[1]));
}

// ---------------------------------------------------------------------------
// Stage one 128x128 bf16 hi/lo A-chunk into ping-pong SMEM buffer (cp.async)
// A global: [b][512]; chunk kc covers k in [kc*128, kc*128+128)
// SMEM: row*256B, 16B unit u placed at (u ^ (row&15))
// ---------------------------------------------------------------------------
__device__ __forceinline__ void issue_chunk(uint32_t sb,
                                            const __nv_bfloat16* __restrict__ hi,
                                            const __nv_bfloat16* __restrict__ lo,
                                            int kc, int buf, int tid) {
    uint32_t base = sb + ABUF(buf);
#pragma unroll
    for (int i = 0; i < 8; ++i) {
        int idx = i * NTHR + tid;
        int row = idx >> 4;
        int u   = idx & 15;
        uint32_t dst = base + row * 256 + ((u ^ (row & 15)) << 4);
        size_t s = (size_t)row * HH + kc * 128 + u * 8;
        cpa16(dst, hi + s);
        cpa16(dst + 32768, lo + s);
    }
    asm volatile("cp.async.commit_group;");
}

// ---------------------------------------------------------------------------
// Compute one chunk: warp w owns batch rows 16w..16w+15; C[16x16] per warp.
// 8 k-steps x (A hi/lo ldmatrix.x4 + per-ntile B hi/lo ldmatrix.x2 + 3 mma).
// ---------------------------------------------------------------------------
__device__ __forceinline__ void compute_chunk(uint32_t sb, int buf, int kc,
                                              uint32_t wHi, uint32_t wLo,
                                              float acc[2][4], int wid, int lane) {
    uint32_t aBase = sb + ABUF(buf);
    int R = wid * 16 + (lane & 15);
    uint32_t arow = aBase + R * 256;
    int n7 = lane & 7;
#pragma unroll
    for (int kk = 0; kk < 8; ++kk) {
        uint32_t ahi[4], alo[4];
        int ua = kk * 2 + (lane >> 4);
        uint32_t aaddr = arow + ((uint32_t)(ua ^ (R & 15)) << 4);
        ldm4(ahi, aaddr);
        ldm4(alo, aaddr + 32768);
#pragma unroll
        for (int nt = 0; nt < 2; ++nt) {
            int n  = nt * 8 + n7;
            int ug = (kc * 8 + kk) * 2 + ((lane >> 3) & 1);
            uint32_t boff = (uint32_t)(n * 1024 + ((ug ^ n7) << 4));
            uint32_t bhi[2], blo[2];
            ldm2(bhi, sb + wHi + boff);
            ldm2(blo, sb + wLo + boff);
            mma16816(acc[nt], ahi, bhi);
            mma16816(acc[nt], ahi, blo);
            mma16816(acc[nt], alo, bhi);
        }
    }
}

// Store per-warp C frags to SMEM gate buffer G[col][row] (16 x 128 f32)
__device__ __forceinline__ void frag_to_smem(float* G, const float acc[2][4],
                                             int wid, int lane) {
    int r = wid * 16 + (lane >> 2);
#pragma unroll
    for (int nt = 0; nt < 2; ++nt) {
        int col = nt * 8 + 2 * (lane & 3);
        G[col * 128 + r]           = acc[nt][0];
        G[(col + 1) * 128 + r]     = acc[nt][1];
        G[col * 128 + r + 8]       = acc[nt][2];
        G[(col + 1) * 128 + r + 8] = acc[nt][3];
    }
}

// ---------------------------------------------------------------------------
// Persistent HMMA LSTM. CTA c owns hidden units [4c,4c+4) for both layers.
// ---------------------------------------------------------------------------
__global__ void __launch_bounds__(NTHR, 1)
lstm_persist(const float* __restrict__ x,
             const float* __restrict__ Wih1, const float* __restrict__ Whh1,
             const float* __restrict__ bih1, const float* __restrict__ bhh1,
             const float* __restrict__ Wih2, const float* __restrict__ Whh2,
             const float* __restrict__ bih2, const float* __restrict__ bhh2,
             const float* __restrict__ Wlin) {
    extern __shared__ char smem[];
    const uint32_t sb = smem_u32(smem);
    const int cta = blockIdx.x;
    const int tid = threadIdx.x;
    const int wid = tid >> 5;
    const int lane = tid & 31;

    float* bias1 = (float*)(smem + MISC);
    float* wih1  = (float*)(smem + MISC + 64);
    float* bias2 = (float*)(smem + MISC + 128);

    // ---- Prologue: weights -> SMEM bf16 hi/lo, [n][k] with XOR-16B swizzle ----
    for (int m = 0; m < 3; ++m) {
        const float* W = (m == 0) ? Whh1 : (m == 1) ? Whh2 : Wih2;
        uint32_t hiO = WOFF + m * 32768u, loO = hiO + 16384u;
        for (int q = tid; q < 8192; q += NTHR) {
            int n = q >> 9, k = q & 511;
            int R = (n >> 2) * HH + cta * 4 + (n & 3);   // gate-interleaved row
            float w = W[R * HH + k];
            __nv_bfloat16 wh = __float2bfloat16(w);
            __nv_bfloat16 wl = __float2bfloat16(w - __bfloat162float(wh));
            uint32_t off = (uint32_t)(n * 1024 + (((k >> 3) ^ (n & 7)) << 4) +
                                      (k & 7) * 2);
            *(__nv_bfloat16*)(smem + hiO + off) = wh;
            *(__nv_bfloat16*)(smem + loO + off) = wl;
        }
    }
    if (tid < 16) {
        int n = tid;
        int R = (n >> 2) * HH + cta * 4 + (n & 3);
        bias1[n] = bih1[R] + bhh1[R];
        wih1[n]  = Wih1[R];                              // W_ih1 is [4H, 1]
        bias2[n] = bih2[R] + bhh2[R];
    }

    // ---- Global init: zero h states, transpose x and W_lin ----
    const int gtid = cta * NTHR + tid;
    const int gstr = NCTA * NTHR;
    const __nv_bfloat16 z16 = __float2bfloat16(0.0f);
    for (int i = gtid; i < BB * HH; i += gstr) {
        g_h1hi[0][i] = z16; g_h1hi[1][i] = z16;
        g_h1lo[0][i] = z16; g_h1lo[1][i] = z16;
        g_h2hi[i] = z16;    g_h2lo[i] = z16;
    }
    for (int i = gtid; i < TT * BB; i += gstr) {
        int t = i >> 7, b = i & (BB - 1);
        g_xT[i] = x[b * TT + t];
    }
    for (int i = gtid; i < HH * VV; i += gstr) {
        int k = i >> 8, v = i & (VV - 1);
        g_WlinT[i] = Wlin[v * HH + k];
    }
    __syncthreads();
    grid_barrier();

    // ---- Time loop ----
    float c1st[2] = {0, 0}, c2st[2] = {0, 0};
    float* G = (float*)smem;          // gate-exchange buffer aliases A-buf0

    for (int t = 0; t < TT; ++t) {
        const int hp = t & 1;
        float acc1[2][4] = {{0, 0, 0, 0}, {0, 0, 0, 0}};
        float acc2[2][4] = {{0, 0, 0, 0}, {0, 0, 0, 0}};

        // ===== phase A: GEMM1 (h1_prev @ W1^T) + GEMM2 (h2_prev @ W2h^T) =====
        issue_chunk(sb, g_h1hi[hp], g_h1lo[hp], 0, 0, tid);
        for (int c = 0; c < 8; ++c) {
            if (c < 7) {
                const __nv_bfloat16* sh = (c + 1 < 4) ? g_h1hi[hp] : g_h2hi;
                const __nv_bfloat16* sl = (c + 1 < 4) ? g_h1lo[hp] : g_h2lo;
                issue_chunk(sb, sh, sl, (c + 1) & 3, (c + 1) & 1, tid);
                asm volatile("cp.async.wait_group 1;");
            } else {
                asm volatile("cp.async.wait_group 0;");
            }
            __syncthreads();
            if (c < 4) compute_chunk(sb, c & 1, c, W1HI, W1LO, acc1, wid, lane);
            else       compute_chunk(sb, c & 1, c & 3, W2HHI, W2HLO, acc2, wid, lane);
            __syncthreads();
        }

        // ===== epilogue 1: layer-1 activation -> h1_new (bf16 hi/lo) =====
        frag_to_smem(G, acc1, wid, lane);
        __syncthreads();
        {
            int row = tid & 127, up = tid >> 7;
            float xv = g_xT[t * BB + row];
            union { uint32_t u; __nv_bfloat16 h[2]; } ph, pl;
#pragma unroll
            for (int q = 0; q < 2; ++q) {
                int uu = 2 * up + q;
                float gi = G[uu * 128 + row]        + bias1[uu]      + xv * wih1[uu];
                float gf = G[(4 + uu) * 128 + row]  + bias1[4 + uu]  + xv * wih1[4 + uu];
                float gg = G[(8 + uu) * 128 + row]  + bias1[8 + uu]  + xv * wih1[8 + uu];
                float go = G[(12 + uu) * 128 + row] + bias1[12 + uu] + xv * wih1[12 + uu];
                float cn = sigf(gf) * c1st[q] + sigf(gi) * tanhf(gg);
                c1st[q] = cn;
                float h = sigf(go) * tanhf(cn);
                ph.h[q] = __float2bfloat16(h);
                pl.h[q] = __float2bfloat16(h - __bfloat162float(ph.h[q]));
            }
            size_t o = (size_t)row * HH + cta * 4 + 2 * up;
            *(uint32_t*)&g_h1hi[1 - hp][o] = ph.u;
            *(uint32_t*)&g_h1lo[1 - hp][o] = pl.u;
        }

        grid_barrier();   // h1_new visible; all h2_prev reads done

        // ===== phase B: GEMM3 (h1_new @ W2i^T), accumulates into acc2 regs =====
        issue_chunk(sb, g_h1hi[1 - hp], g_h1lo[1 - hp], 0, 0, tid);
        for (int c = 0; c < 4; ++c) {
            if (c < 3) {
                issue_chunk(sb, g_h1hi[1 - hp], g_h1lo[1 - hp], c + 1, (c + 1) & 1, tid);
                asm volatile("cp.async.wait_group 1;");
            } else {
                asm volatile("cp.async.wait_group 0;");
            }
            __syncthreads();
            compute_chunk(sb, c & 1, c, W2IHI, W2ILO, acc2, wid, lane);
            __syncthreads();
        }

        // ===== epilogue 2: layer-2 activation -> h2 (bf16 hi/lo) + h2all =====
        frag_to_smem(G, acc2, wid, lane);
        __syncthreads();
        {
            int row = tid & 127, up = tid >> 7;
            union { uint32_t u; __nv_bfloat16 h[2]; } ph, pl;
#pragma unroll
            for (int q = 0; q < 2; ++q) {
                int uu = 2 * up + q;
                float gi = G[uu * 128 + row]        + bias2[uu];
                float gf = G[(4 + uu) * 128 + row]  + bias2[4 + uu];
                float gg = G[(8 + uu) * 128 + row]  + bias2[8 + uu];
                float go = G[(12 + uu) * 128 + row] + bias2[12 + uu];
                float cn = sigf(gf) * c2st[q] + sigf(gi) * tanhf(gg);
                c2st[q] = cn;
                float h = sigf(go) * tanhf(cn);
                ph.h[q] = __float2bfloat16(h);
                pl.h[q] = __float2bfloat16(h - __bfloat162float(ph.h[q]));
                g_h2all[(size_t)t * (HH * BB) + (cta * 4 + uu) * BB + row] = h;
            }
            size_t o = (size_t)row * HH + cta * 4 + 2 * up;
            *(uint32_t*)&g_h2hi[o] = ph.u;
            *(uint32_t*)&g_h2lo[o] = pl.u;
        }

        grid_barrier();   // h2_new visible; A-buffers free for next step
    }
}

// ---------------------------------------------------------------------------
// Final phase: logits = h2_all @ W_lin^T + b_lin, softmax over V (unchanged)
// ---------------------------------------------------------------------------
__global__ void __launch_bounds__(NTHR)
lin_softmax(const float* __restrict__ blin, float* __restrict__ out) {
    __shared__ float w_s[32 * VV];
    const int bx = blockIdx.x;
    const int t  = bx >> 2;
    const int bbk = bx & 3;
    const int tid = threadIdx.x;
    const int tb = tid >> 5;
    const int tc = tid & 31;

    float acc[4][8];
#pragma unroll
    for (int i = 0; i < 4; ++i)
#pragma unroll
        for (int j = 0; j < 8; ++j) acc[i][j] = 0.0f;

    for (int k0 = 0; k0 < HH; k0 += 32) {
        __syncthreads();
        for (int i = tid; i < 32 * VV; i += NTHR)
            w_s[i] = g_WlinT[k0 * VV + i];
        __syncthreads();
#pragma unroll 8
        for (int kk = 0; kk < 32; ++kk) {
            float4 hv = *(const float4*)&g_h2all[(size_t)t * (HH * BB) +
                                                 (k0 + kk) * BB + bbk * 32 + tb * 4];
            float4 w0 = *(const float4*)&w_s[kk * VV + tc * 8];
            float4 w1 = *(const float4*)&w_s[kk * VV + tc * 8 + 4];
            float hb[4] = {hv.x, hv.y, hv.z, hv.w};
            float wc[8] = {w0.x, w0.y, w0.z, w0.w, w1.x, w1.y, w1.z, w1.w};
#pragma unroll
            for (int bi = 0; bi < 4; ++bi)
#pragma unroll
                for (int vj = 0; vj < 8; ++vj)
                    acc[bi][vj] = fmaf(hb[bi], wc[vj], acc[bi][vj]);
        }
    }

    float lb[8];
    *(float4*)&lb[0] = *(const float4*)&blin[tc * 8];
    *(float4*)&lb[4] = *(const float4*)&blin[tc * 8 + 4];

#pragma unroll
    for (int bi = 0; bi < 4; ++bi) {
        float m = -1e30f;
#pragma unroll
        for (int vj = 0; vj < 8; ++vj) {
            acc[bi][vj] += lb[vj];
            m = fmaxf(m, acc[bi][vj]);
        }
#pragma unroll
        for (int off = 16; off >= 1; off >>= 1)
            m = fmaxf(m, __shfl_xor_sync(0xffffffffu, m, off));
        float s = 0.0f;
#pragma unroll
        for (int vj = 0; vj < 8; ++vj) {
            float e = expf(acc[bi][vj] - m);
            acc[bi][vj] = e;
            s += e;
        }
#pragma unroll
        for (int off = 16; off >= 1; off >>= 1)
            s += __shfl_xor_sync(0xffffffffu, s, off);
        float inv = 1.0f / s;
        size_t b = (size_t)(bbk * 32 + tb * 4 + bi);
        float4 o0 = make_float4(acc[bi][0] * inv, acc[bi][1] * inv,
                                acc[bi][2] * inv, acc[bi][3] * inv);
        float4 o1 = make_float4(acc[bi][4] * inv, acc[bi][5] * inv,
                                acc[bi][6] * inv, acc[bi][7] * inv);
        float* op = out + b * ((size_t)TT * VV) + (size_t)t * VV + tc * 8;
        *(float4*)op       = o0;
        *(float4*)(op + 4) = o1;
    }
}

// ---------------------------------------------------------------------------
extern "C" void kernel_launch(void* const* d_in, const int* in_sizes, int n_in,
                              void* d_out, int out_size) {
    const float* x    = (const float*)d_in[0];
    const float* Wih1 = (const float*)d_in[1];
    const float* Whh1 = (const float*)d_in[2];
    const float* bih1 = (const float*)d_in[3];
    const float* bhh1 = (const float*)d_in[4];
    const float* Wih2 = (const float*)d_in[5];
    const float* Whh2 = (const float*)d_in[6];
    const float* bih2 = (const float*)d_in[7];
    const float* bhh2 = (const float*)d_in[8];
    const float* Wlin = (const float*)d_in[9];
    const float* blin = (const float*)d_in[10];

    cudaFuncSetAttribute(lstm_persist, cudaFuncAttributeMaxDynamicSharedMemorySize,
                         SMEM_TOTAL);

    lstm_persist<<<NCTA, NTHR, SMEM_TOTAL>>>(x, Wih1, Whh1, bih1, bhh1,
                                             Wih2, Whh2, bih2, bhh2, Wlin);
    lin_softmax<<<TT * 4, NTHR>>>(blin, (float*)d_out);
}

// round 6
// speedup vs baseline: 3.1841x; 1.5635x over previous
#include <cuda_runtime.h>
#include <cuda_fp16.h>
#include <cstdint>

#define BB   128
#define TT   1024
#define HH   512
#define VV   256
#define NCTA 128
#define NTHR 256

// ---------------------------------------------------------------------------
// Device scratch (allocation-free). h matrices fp16, layout [b][k].
// ---------------------------------------------------------------------------
__device__ __half g_h1[BB * HH];                  // single buffer (see schedule)
__device__ __half g_h2[BB * HH];
__device__ float g_xT[TT * BB];                   // x transposed [t][b]
__device__ float g_WlinT[HH * VV];                // W_lin transposed [k][v]
__device__ float g_h2all[(size_t)TT * HH * BB];   // [t][j][b] fp32
__device__ unsigned g_barcnt, g_bargen;

// ---------------------------------------------------------------------------
// SMEM layout (bytes)
// 4 A-slots (128x128 fp16, 256B rows, XOR-16B swizzle) = 128 KB
//   - slots double as persistent h1 cache across steps (phase B fills them)
// 3 W arrays [n=16][k=512] fp16, XOR-16B swizzle = 48 KB
// G gate-exchange buffer 16x128 f32 = 8 KB (dedicated; slots stay live)
// ---------------------------------------------------------------------------
#define SLOT(c)   ((c) * 32768)
#define W1O       131072
#define W2HO      (W1O + 16384)
#define W2IO      (W1O + 32768)
#define GOFF      (W1O + 49152)
#define MISC      (GOFF + 8192)
#define SMEM_TOTAL (MISC + 256)

__device__ __forceinline__ uint32_t smem_u32(const void* p) {
    uint32_t a;
    asm("{ .reg .u64 t; cvta.to.shared.u64 t, %1; cvt.u32.u64 %0, t; }"
        : "=r"(a) : "l"(p));
    return a;
}
__device__ __forceinline__ float sigf(float x) { return 1.0f / (1.0f + expf(-x)); }

// ---------------------------------------------------------------------------
// Grid-wide barrier (128 resident CTAs; proven R3/R5)
// ---------------------------------------------------------------------------
__device__ __forceinline__ void grid_barrier() {
    __threadfence();
    __syncthreads();
    if (threadIdx.x == 0) {
        unsigned gen = *(volatile unsigned*)&g_bargen;
        unsigned arrived = atomicAdd(&g_barcnt, 1u);
        if (arrived == NCTA - 1) {
            *(volatile unsigned*)&g_barcnt = 0u;
            __threadfence();
            atomicAdd(&g_bargen, 1u);
        } else {
            while (*(volatile unsigned*)&g_bargen == gen) { }
        }
    }
    __syncthreads();
    __threadfence();
}

// ---------------------------------------------------------------------------
// Primitives (base-target-safe)
// ---------------------------------------------------------------------------
__device__ __forceinline__ void cpa16(uint32_t dst, const void* src) {
    asm volatile("cp.async.cg.shared.global [%0], [%1], 16;" :: "r"(dst), "l"(src));
}
__device__ __forceinline__ void ldm4(uint32_t a[4], uint32_t addr) {
    asm volatile("ldmatrix.sync.aligned.m8n8.x4.shared.b16 {%0,%1,%2,%3}, [%4];"
                 : "=r"(a[0]), "=r"(a[1]), "=r"(a[2]), "=r"(a[3]) : "r"(addr));
}
__device__ __forceinline__ void mma16816(float d[4], const uint32_t a[4],
                                         const uint32_t b0, const uint32_t b1) {
    asm volatile(
        "mma.sync.aligned.m16n8k16.row.col.f32.f16.f16.f32 "
        "{%0,%1,%2,%3}, {%4,%5,%6,%7}, {%8,%9}, {%0,%1,%2,%3};"
        : "+f"(d[0]), "+f"(d[1]), "+f"(d[2]), "+f"(d[3])
        : "r"(a[0]), "r"(a[1]), "r"(a[2]), "r"(a[3]), "r"(b0), "r"(b1));
}

// ---------------------------------------------------------------------------
// Stage one 128x128 fp16 A-chunk into slot (cp.async, one group committed).
// Global A: [b][512]; chunk kc covers k in [kc*128, kc*128+128).
// SMEM: row*256B; 16B-unit u at (u ^ (row & 15)).
// ---------------------------------------------------------------------------
__device__ __forceinline__ void issue_chunk(uint32_t sb, const __half* __restrict__ src,
                                            int kc, int slot, int tid) {
    uint32_t base = sb + SLOT(slot);
#pragma unroll
    for (int i = 0; i < 8; ++i) {
        int idx = i * NTHR + tid;
        int row = idx >> 4;
        int u   = idx & 15;
        uint32_t dst = base + row * 256 + ((u ^ (row & 15)) << 4);
        cpa16(dst, src + (size_t)row * HH + kc * 128 + u * 8);
    }
    asm volatile("cp.async.commit_group;");
}

// ---------------------------------------------------------------------------
// Compute one chunk: warp w owns batch rows 16w..16w+15, C[16x16] per warp.
// Per k-step: one ldmatrix.x4 for A (m16k16), one ldmatrix.x4 for B
// (both n-tiles' k16n8 frags), 2 mma. Addressing proven in R5.
// ---------------------------------------------------------------------------
__device__ __forceinline__ void compute_chunk(uint32_t sb, int slot, int kc,
                                              uint32_t wOff, float acc[2][4],
                                              int wid, int lane) {
    uint32_t arow = sb + SLOT(slot) + (wid * 16 + (lane & 15)) * 256;
    int Ra = (wid * 16 + (lane & 15)) & 15;
    int nn = (lane & 7) + ((lane >> 4) << 3);       // B: n-row for this lane
    int n7 = lane & 7;
#pragma unroll
    for (int kk = 0; kk < 8; ++kk) {
        uint32_t a[4];
        int ua = kk * 2 + (lane >> 4);
        ldm4(a, arow + ((uint32_t)(ua ^ Ra) << 4));
        uint32_t b[4];
        int ug = (kc * 8 + kk) * 2 + ((lane >> 3) & 1);
        ldm4(b, sb + wOff + (uint32_t)(nn * 1024 + ((ug ^ n7) << 4)));
        mma16816(acc[0], a, b[0], b[1]);
        mma16816(acc[1], a, b[2], b[3]);
    }
}

// Store per-warp C frags to gate buffer G[col][row] (16 x 128 f32)
__device__ __forceinline__ void frag_to_smem(float* G, const float acc[2][4],
                                             int wid, int lane) {
    int r = wid * 16 + (lane >> 2);
#pragma unroll
    for (int nt = 0; nt < 2; ++nt) {
        int col = nt * 8 + 2 * (lane & 3);
        G[col * 128 + r]           = acc[nt][0];
        G[(col + 1) * 128 + r]     = acc[nt][1];
        G[col * 128 + r + 8]       = acc[nt][2];
        G[(col + 1) * 128 + r + 8] = acc[nt][3];
    }
}

// ---------------------------------------------------------------------------
// Persistent HMMA LSTM. CTA c owns hidden units [4c,4c+4) for both layers.
// ---------------------------------------------------------------------------
__global__ void __launch_bounds__(NTHR, 1)
lstm_persist(const float* __restrict__ x,
             const float* __restrict__ Wih1, const float* __restrict__ Whh1,
             const float* __restrict__ bih1, const float* __restrict__ bhh1,
             const float* __restrict__ Wih2, const float* __restrict__ Whh2,
             const float* __restrict__ bih2, const float* __restrict__ bhh2,
             const float* __restrict__ Wlin) {
    extern __shared__ char smem[];
    const uint32_t sb = smem_u32(smem);
    const int cta = blockIdx.x;
    const int tid = threadIdx.x;
    const int wid = tid >> 5;
    const int lane = tid & 31;

    float* G     = (float*)(smem + GOFF);
    float* bias1 = (float*)(smem + MISC);
    float* wih1  = (float*)(smem + MISC + 64);
    float* bias2 = (float*)(smem + MISC + 128);

    // ---- Prologue: weights -> SMEM fp16 [n][k], XOR-16B swizzle ----
    for (int m = 0; m < 3; ++m) {
        const float* W = (m == 0) ? Whh1 : (m == 1) ? Whh2 : Wih2;
        uint32_t wO = W1O + m * 16384u;
        for (int q = tid; q < 8192; q += NTHR) {
            int n = q >> 9, k = q & 511;
            int R = (n >> 2) * HH + cta * 4 + (n & 3);   // gate-interleaved row
            uint32_t off = (uint32_t)(n * 1024 + (((k >> 3) ^ (n & 7)) << 4) +
                                      (k & 7) * 2);
            *(__half*)(smem + wO + off) = __float2half(W[R * HH + k]);
        }
    }
    if (tid < 16) {
        int n = tid;
        int R = (n >> 2) * HH + cta * 4 + (n & 3);
        bias1[n] = bih1[R] + bhh1[R];
        wih1[n]  = Wih1[R];                              // W_ih1 is [4H, 1]
        bias2[n] = bih2[R] + bhh2[R];
    }

    // ---- Global init: zero h states, transpose x and W_lin ----
    const int gtid = cta * NTHR + tid;
    const int gstr = NCTA * NTHR;
    const __half z16 = __float2half(0.0f);
    for (int i = gtid; i < BB * HH; i += gstr) { g_h1[i] = z16; g_h2[i] = z16; }
    for (int i = gtid; i < TT * BB; i += gstr) {
        int t = i >> 7, b = i & (BB - 1);
        g_xT[i] = x[b * TT + t];
    }
    for (int i = gtid; i < HH * VV; i += gstr) {
        int k = i >> 8, v = i & (VV - 1);
        g_WlinT[i] = Wlin[v * HH + k];
    }
    // zero A-slots (h1_prev = 0 for t=0 GEMM1)
    for (int i = tid; i < 32768; i += NTHR) ((uint32_t*)smem)[i] = 0u;
    __syncthreads();
    grid_barrier();

    // ---- Time loop ----
    float c1st[2] = {0, 0}, c2st[2] = {0, 0};

    for (int t = 0; t < TT; ++t) {
        float acc1[2][4] = {{0, 0, 0, 0}, {0, 0, 0, 0}};
        float acc2[2][4] = {{0, 0, 0, 0}, {0, 0, 0, 0}};

        // ===== phase A =====
        // iters 0-3: GEMM1 chunk c from cached slot c (h1_prev), then refill
        //            slot c with h2 chunk c (cp.async group per chunk).
        // iters 4-7: GEMM2 chunk c-4 from slot c-4 (h2_prev).
#pragma unroll
        for (int c = 0; c < 8; ++c) {
            if (c == 4) asm volatile("cp.async.wait_group 3;");
            if (c == 5) asm volatile("cp.async.wait_group 2;");
            if (c == 6) asm volatile("cp.async.wait_group 1;");
            if (c == 7) asm volatile("cp.async.wait_group 0;");
            if (c >= 4) __syncthreads();
            if (c < 4) {
                compute_chunk(sb, c, c, W1O, acc1, wid, lane);
                __syncthreads();                      // all reads of slot c done
                issue_chunk(sb, g_h2, c, c, tid);     // overwrite with h2 chunk c
            } else {
                compute_chunk(sb, c - 4, c - 4, W2HO, acc2, wid, lane);
            }
        }

        // ===== epilogue 1: layer-1 activation -> h1_new fp16 =====
        frag_to_smem(G, acc1, wid, lane);
        __syncthreads();
        {
            int row = tid & 127, up = tid >> 7;
            float xv = g_xT[t * BB + row];
            union { uint32_t u; __half h[2]; } ph;
#pragma unroll
            for (int q = 0; q < 2; ++q) {
                int uu = 2 * up + q;
                float gi = G[uu * 128 + row]        + bias1[uu]      + xv * wih1[uu];
                float gf = G[(4 + uu) * 128 + row]  + bias1[4 + uu]  + xv * wih1[4 + uu];
                float gg = G[(8 + uu) * 128 + row]  + bias1[8 + uu]  + xv * wih1[8 + uu];
                float go = G[(12 + uu) * 128 + row] + bias1[12 + uu] + xv * wih1[12 + uu];
                float cn = sigf(gf) * c1st[q] + sigf(gi) * tanhf(gg);
                c1st[q] = cn;
                ph.h[q] = __float2half(sigf(go) * tanhf(cn));
            }
            *(uint32_t*)&g_h1[(size_t)row * HH + cta * 4 + 2 * up] = ph.u;
        }

        grid_barrier();   // h1_new visible; all h2_prev reads done

        // ===== phase B: GEMM3 (h1_new @ W2i^T) into acc2; slots become the
        //       h1 cache consumed by next step's GEMM1 =====
#pragma unroll
        for (int c = 0; c < 4; ++c) issue_chunk(sb, g_h1, c, c, tid);
#pragma unroll
        for (int c = 0; c < 4; ++c) {
            if (c == 0) asm volatile("cp.async.wait_group 3;");
            if (c == 1) asm volatile("cp.async.wait_group 2;");
            if (c == 2) asm volatile("cp.async.wait_group 1;");
            if (c == 3) asm volatile("cp.async.wait_group 0;");
            __syncthreads();
            compute_chunk(sb, c, c, W2IO, acc2, wid, lane);
        }

        // ===== epilogue 2: layer-2 activation -> h2 fp16 + h2all fp32 =====
        frag_to_smem(G, acc2, wid, lane);
        __syncthreads();
        {
            int row = tid & 127, up = tid >> 7;
            union { uint32_t u; __half h[2]; } ph;
#pragma unroll
            for (int q = 0; q < 2; ++q) {
                int uu = 2 * up + q;
                float gi = G[uu * 128 + row]        + bias2[uu];
                float gf = G[(4 + uu) * 128 + row]  + bias2[4 + uu];
                float gg = G[(8 + uu) * 128 + row]  + bias2[8 + uu];
                float go = G[(12 + uu) * 128 + row] + bias2[12 + uu];
                float cn = sigf(gf) * c2st[q] + sigf(gi) * tanhf(gg);
                c2st[q] = cn;
                float h = sigf(go) * tanhf(cn);
                ph.h[q] = __float2half(h);
                g_h2all[(size_t)t * (HH * BB) + (cta * 4 + uu) * BB + row] = h;
            }
            *(uint32_t*)&g_h2[(size_t)row * HH + cta * 4 + 2 * up] = ph.u;
        }

        grid_barrier();   // h2_new visible; slots hold h1 cache for next step
    }
}

// ---------------------------------------------------------------------------
// Final phase: logits = h2_all @ W_lin^T + b_lin, softmax over V (unchanged)
// ---------------------------------------------------------------------------
__global__ void __launch_bounds__(NTHR)
lin_softmax(const float* __restrict__ blin, float* __restrict__ out) {
    __shared__ float w_s[32 * VV];
    const int bx = blockIdx.x;
    const int t  = bx >> 2;
    const int bbk = bx & 3;
    const int tid = threadIdx.x;
    const int tb = tid >> 5;
    const int tc = tid & 31;

    float acc[4][8];
#pragma unroll
    for (int i = 0; i < 4; ++i)
#pragma unroll
        for (int j = 0; j < 8; ++j) acc[i][j] = 0.0f;

    for (int k0 = 0; k0 < HH; k0 += 32) {
        __syncthreads();
        for (int i = tid; i < 32 * VV; i += NTHR)
            w_s[i] = g_WlinT[k0 * VV + i];
        __syncthreads();
#pragma unroll 8
        for (int kk = 0; kk < 32; ++kk) {
            float4 hv = *(const float4*)&g_h2all[(size_t)t * (HH * BB) +
                                                 (k0 + kk) * BB + bbk * 32 + tb * 4];
            float4 w0 = *(const float4*)&w_s[kk * VV + tc * 8];
            float4 w1 = *(const float4*)&w_s[kk * VV + tc * 8 + 4];
            float hb[4] = {hv.x, hv.y, hv.z, hv.w};
            float wc[8] = {w0.x, w0.y, w0.z, w0.w, w1.x, w1.y, w1.z, w1.w};
#pragma unroll
            for (int bi = 0; bi < 4; ++bi)
#pragma unroll
                for (int vj = 0; vj < 8; ++vj)
                    acc[bi][vj] = fmaf(hb[bi], wc[vj], acc[bi][vj]);
        }
    }

    float lb[8];
    *(float4*)&lb[0] = *(const float4*)&blin[tc * 8];
    *(float4*)&lb[4] = *(const float4*)&blin[tc * 8 + 4];

#pragma unroll
    for (int bi = 0; bi < 4; ++bi) {
        float m = -1e30f;
#pragma unroll
        for (int vj = 0; vj < 8; ++vj) {
            acc[bi][vj] += lb[vj];
            m = fmaxf(m, acc[bi][vj]);
        }
#pragma unroll
        for (int off = 16; off >= 1; off >>= 1)
            m = fmaxf(m, __shfl_xor_sync(0xffffffffu, m, off));
        float s = 0.0f;
#pragma unroll
        for (int vj = 0; vj < 8; ++vj) {
            float e = expf(acc[bi][vj] - m);
            acc[bi][vj] = e;
            s += e;
        }
#pragma unroll
        for (int off = 16; off >= 1; off >>= 1)
            s += __shfl_xor_sync(0xffffffffu, s, off);
        float inv = 1.0f / s;
        size_t b = (size_t)(bbk * 32 + tb * 4 + bi);
        float4 o0 = make_float4(acc[bi][0] * inv, acc[bi][1] * inv,
                                acc[bi][2] * inv, acc[bi][3] * inv);
        float4 o1 = make_float4(acc[bi][4] * inv, acc[bi][5] * inv,
                                acc[bi][6] * inv, acc[bi][7] * inv);
        float* op = out + b * ((size_t)TT * VV) + (size_t)t * VV + tc * 8;
        *(float4*)op       = o0;
        *(float4*)(op + 4) = o1;
    }
}

// ---------------------------------------------------------------------------
extern "C" void kernel_launch(void* const* d_in, const int* in_sizes, int n_in,
                              void* d_out, int out_size) {
    const float* x    = (const float*)d_in[0];
    const float* Wih1 = (const float*)d_in[1];
    const float* Whh1 = (const float*)d_in[2];
    const float* bih1 = (const float*)d_in[3];
    const float* bhh1 = (const float*)d_in[4];
    const float* Wih2 = (const float*)d_in[5];
    const float* Whh2 = (const float*)d_in[6];
    const float* bih2 = (const float*)d_in[7];
    const float* bhh2 = (const float*)d_in[8];
    const float* Wlin = (const float*)d_in[9];
    const float* blin = (const float*)d_in[10];

    cudaFuncSetAttribute(lstm_persist, cudaFuncAttributeMaxDynamicSharedMemorySize,
                         SMEM_TOTAL);

    lstm_persist<<<NCTA, NTHR, SMEM_TOTAL>>>(x, Wih1, Whh1, bih1, bhh1,
                                             Wih2, Whh2, bih2, bhh2, Wlin);
    lin_softmax<<<TT * 4, NTHR>>>(blin, (float*)d_out);
}

// round 7
// speedup vs baseline: 3.5589x; 1.1177x over previous
#include <cuda_runtime.h>
#include <cuda_fp16.h>
#include <cstdint>

#define BB   128
#define TT   1024
#define HH   512
#define VV   256
#define NCTA 128
#define NTHR 256

// ---------------------------------------------------------------------------
// Device scratch (allocation-free). h matrices fp16, layout [b][k].
// g_h2 double-buffered (split-phase barriers relax WAR ordering).
// ---------------------------------------------------------------------------
__device__ __half g_h1[BB * HH];
__device__ __half g_h2[2][BB * HH];
__device__ float g_xT[TT * BB];
__device__ float g_WlinT[HH * VV];
__device__ float g_h2all[(size_t)TT * HH * BB];   // [t][j][b] fp32
__device__ unsigned g_barcnt, g_bargen;           // old-style init barrier
__device__ unsigned g_cnt[2], g_gen[2];           // split-phase barriers

// ---------------------------------------------------------------------------
// SMEM: 4 A-slots (128x128 fp16, 256B rows, XOR-16B swizzle) = 128 KB
//       3 W arrays [n=16][k=512] fp16 = 48 KB ; G gate buffer 8 KB
// ---------------------------------------------------------------------------
#define SLOT(c)   ((c) * 32768)
#define W1O       131072
#define W2HO      (W1O + 16384)
#define W2IO      (W1O + 32768)
#define GOFF      (W1O + 49152)
#define MISC      (GOFF + 8192)
#define SMEM_TOTAL (MISC + 256)

__device__ __forceinline__ uint32_t smem_u32(const void* p) {
    uint32_t a;
    asm("{ .reg .u64 t; cvta.to.shared.u64 t, %1; cvt.u32.u64 %0, t; }"
        : "=r"(a) : "l"(p));
    return a;
}
// Fast activations (saturation-safe; __expf(±inf) paths give exact limits)
__device__ __forceinline__ float sigf(float x) {
    return __fdividef(1.0f, 1.0f + __expf(-x));
}
__device__ __forceinline__ float tanhf_fast(float x) {
    return 1.0f - __fdividef(2.0f, __expf(2.0f * x) + 1.0f);
}

// ---------------------------------------------------------------------------
// Old-style relative grid barrier (replay-safe) — init only
// ---------------------------------------------------------------------------
__device__ __forceinline__ void grid_barrier() {
    __threadfence();
    __syncthreads();
    if (threadIdx.x == 0) {
        unsigned gen = *(volatile unsigned*)&g_bargen;
        unsigned arrived = atomicAdd(&g_barcnt, 1u);
        if (arrived == NCTA - 1) {
            *(volatile unsigned*)&g_barcnt = 0u;
            __threadfence();
            atomicAdd(&g_bargen, 1u);
        } else {
            while (*(volatile unsigned*)&g_bargen == gen) { }
        }
    }
    __syncthreads();
    __threadfence();
}

// ---------------------------------------------------------------------------
// Split-phase barriers, monotonic rounds (reset each launch in prologue).
// arrive: release (per-thread fence -> syncthreads -> tid0 atomic).
// wait:   acquire (tid0 spin -> syncthreads -> per-thread fence).
// ---------------------------------------------------------------------------
__device__ __forceinline__ void bar_arrive(int i, unsigned round) {
    __threadfence();
    __syncthreads();
    if (threadIdx.x == 0) {
        unsigned a = atomicAdd(&g_cnt[i], 1u);
        if (a == round * NCTA + (NCTA - 1)) {
            __threadfence();
            atomicExch(&g_gen[i], round + 1u);
        }
    }
}
__device__ __forceinline__ void bar_wait(int i, unsigned round) {
    if (threadIdx.x == 0) {
        while (*(volatile unsigned*)&g_gen[i] < round + 1u) { }
    }
    __syncthreads();
    __threadfence();
}

// ---------------------------------------------------------------------------
// Primitives
// ---------------------------------------------------------------------------
__device__ __forceinline__ void cpa16(uint32_t dst, const void* src) {
    asm volatile("cp.async.cg.shared.global [%0], [%1], 16;" :: "r"(dst), "l"(src));
}
__device__ __forceinline__ void ldm4(uint32_t a[4], uint32_t addr) {
    asm volatile("ldmatrix.sync.aligned.m8n8.x4.shared.b16 {%0,%1,%2,%3}, [%4];"
                 : "=r"(a[0]), "=r"(a[1]), "=r"(a[2]), "=r"(a[3]) : "r"(addr));
}
__device__ __forceinline__ void mma16816(float d[4], const uint32_t a[4],
                                         const uint32_t b0, const uint32_t b1) {
    asm volatile(
        "mma.sync.aligned.m16n8k16.row.col.f32.f16.f16.f32 "
        "{%0,%1,%2,%3}, {%4,%5,%6,%7}, {%8,%9}, {%0,%1,%2,%3};"
        : "+f"(d[0]), "+f"(d[1]), "+f"(d[2]), "+f"(d[3])
        : "r"(a[0]), "r"(a[1]), "r"(a[2]), "r"(a[3]), "r"(b0), "r"(b1));
}

// Stage one 128x128 fp16 A-chunk into slot (one cp.async group).
__device__ __forceinline__ void issue_chunk(uint32_t sb, const __half* __restrict__ src,
                                            int kc, int slot, int tid) {
    uint32_t base = sb + SLOT(slot);
#pragma unroll
    for (int i = 0; i < 8; ++i) {
        int idx = i * NTHR + tid;
        int row = idx >> 4;
        int u   = idx & 15;
        uint32_t dst = base + row * 256 + ((u ^ (row & 15)) << 4);
        cpa16(dst, src + (size_t)row * HH + kc * 128 + u * 8);
    }
    asm volatile("cp.async.commit_group;");
}

// Single-GEMM chunk (addressing proven R5/R6)
__device__ __forceinline__ void compute_chunk(uint32_t sb, int slot, int kc,
                                              uint32_t wOff, float acc[2][4],
                                              int wid, int lane) {
    uint32_t arow = sb + SLOT(slot) + (wid * 16 + (lane & 15)) * 256;
    int Ra = (wid * 16 + (lane & 15)) & 15;
    int nn = (lane & 7) + ((lane >> 4) << 3);
    int n7 = lane & 7;
#pragma unroll
    for (int kk = 0; kk < 8; ++kk) {
        uint32_t a[4];
        int ua = kk * 2 + (lane >> 4);
        ldm4(a, arow + ((uint32_t)(ua ^ Ra) << 4));
        uint32_t b[4];
        int ug = (kc * 8 + kk) * 2 + ((lane >> 3) & 1);
        ldm4(b, sb + wOff + (uint32_t)(nn * 1024 + ((ug ^ n7) << 4)));
        mma16816(acc[0], a, b[0], b[1]);
        mma16816(acc[1], a, b[2], b[3]);
    }
}

// Dual-GEMM chunk: same A frags feed two weight matrices (GEMM3 + next GEMM1)
__device__ __forceinline__ void compute_chunk_dual(uint32_t sb, int slot, int kc,
                                                   uint32_t wA, float accA[2][4],
                                                   uint32_t wB, float accB[2][4],
                                                   int wid, int lane) {
    uint32_t arow = sb + SLOT(slot) + (wid * 16 + (lane & 15)) * 256;
    int Ra = (wid * 16 + (lane & 15)) & 15;
    int nn = (lane & 7) + ((lane >> 4) << 3);
    int n7 = lane & 7;
#pragma unroll
    for (int kk = 0; kk < 8; ++kk) {
        uint32_t a[4];
        int ua = kk * 2 + (lane >> 4);
        ldm4(a, arow + ((uint32_t)(ua ^ Ra) << 4));
        int ug = (kc * 8 + kk) * 2 + ((lane >> 3) & 1);
        uint32_t boff = (uint32_t)(nn * 1024 + ((ug ^ n7) << 4));
        uint32_t b[4], b2[4];
        ldm4(b,  sb + wA + boff);
        ldm4(b2, sb + wB + boff);
        mma16816(accA[0], a, b[0], b[1]);
        mma16816(accA[1], a, b[2], b[3]);
        mma16816(accB[0], a, b2[0], b2[1]);
        mma16816(accB[1], a, b2[2], b2[3]);
    }
}

__device__ __forceinline__ void frag_to_smem(float* G, const float acc[2][4],
                                             int wid, int lane) {
    int r = wid * 16 + (lane >> 2);
#pragma unroll
    for (int nt = 0; nt < 2; ++nt) {
        int col = nt * 8 + 2 * (lane & 3);
        G[col * 128 + r]           = acc[nt][0];
        G[(col + 1) * 128 + r]     = acc[nt][1];
        G[col * 128 + r + 8]       = acc[nt][2];
        G[(col + 1) * 128 + r + 8] = acc[nt][3];
    }
}

// ---------------------------------------------------------------------------
// Persistent HMMA LSTM. CTA c owns hidden units [4c,4c+4) for both layers.
// Schedule per step t:
//   waitB2(t-1); issue h2(t-1) loads; e1(t) [uses acc1 from last step];
//   arriveB1(t); GEMM2 (acc2+=W2h.h2);
//   waitB1(t);  issue h1(t) loads; dual GEMM (acc2+=W2i.h1, acc1'=W1.h1);
//   e2(t); arriveB2(t)
// ---------------------------------------------------------------------------
__global__ void __launch_bounds__(NTHR, 1)
lstm_persist(const float* __restrict__ x,
             const float* __restrict__ Wih1, const float* __restrict__ Whh1,
             const float* __restrict__ bih1, const float* __restrict__ bhh1,
             const float* __restrict__ Wih2, const float* __restrict__ Whh2,
             const float* __restrict__ bih2, const float* __restrict__ bhh2,
             const float* __restrict__ Wlin) {
    extern __shared__ char smem[];
    const uint32_t sb = smem_u32(smem);
    const int cta = blockIdx.x;
    const int tid = threadIdx.x;
    const int wid = tid >> 5;
    const int lane = tid & 31;

    float* G     = (float*)(smem + GOFF);
    float* bias1 = (float*)(smem + MISC);
    float* wih1  = (float*)(smem + MISC + 64);
    float* bias2 = (float*)(smem + MISC + 128);

    // ---- Prologue: weights -> SMEM fp16 [n][k], XOR-16B swizzle ----
    for (int m = 0; m < 3; ++m) {
        const float* W = (m == 0) ? Whh1 : (m == 1) ? Whh2 : Wih2;
        uint32_t wO = W1O + m * 16384u;
        for (int q = tid; q < 8192; q += NTHR) {
            int n = q >> 9, k = q & 511;
            int R = (n >> 2) * HH + cta * 4 + (n & 3);
            uint32_t off = (uint32_t)(n * 1024 + (((k >> 3) ^ (n & 7)) << 4) +
                                      (k & 7) * 2);
            *(__half*)(smem + wO + off) = __float2half(W[R * HH + k]);
        }
    }
    if (tid < 16) {
        int n = tid;
        int R = (n >> 2) * HH + cta * 4 + (n & 3);
        bias1[n] = bih1[R] + bhh1[R];
        wih1[n]  = Wih1[R];
        bias2[n] = bih2[R] + bhh2[R];
    }

    // ---- Global init ----
    const int gtid = cta * NTHR + tid;
    const int gstr = NCTA * NTHR;
    const __half z16 = __float2half(0.0f);
    for (int i = gtid; i < BB * HH; i += gstr) {
        g_h1[i] = z16; g_h2[0][i] = z16; g_h2[1][i] = z16;
    }
    for (int i = gtid; i < TT * BB; i += gstr) {
        int t = i >> 7, b = i & (BB - 1);
        g_xT[i] = x[b * TT + t];
    }
    for (int i = gtid; i < HH * VV; i += gstr) {
        int k = i >> 8, v = i & (VV - 1);
        g_WlinT[i] = Wlin[v * HH + k];
    }
    __syncthreads();
    grid_barrier();
    // reset split-barrier state (persists across graph replays), then publish
    if (cta == 0 && tid == 0) {
        g_cnt[0] = 0u; g_cnt[1] = 0u; g_gen[0] = 0u; g_gen[1] = 0u;
    }
    grid_barrier();

    // ---- Time loop ----
    float c1st[2] = {0, 0}, c2st[2] = {0, 0};
    float acc1[2][4] = {{0, 0, 0, 0}, {0, 0, 0, 0}};   // GEMM1 result (t=0: h1_prev=0)

    for (unsigned t = 0; t < TT; ++t) {
        // ---- wait h2(t-1) producers (hidden behind prior e1/arrive work) ----
        if (t > 0) bar_wait(1, t - 1);

        // ---- prefetch h2(t-1) chunks into slots (overlaps e1 + arrive) ----
        const __half* h2src = g_h2[(t + 1) & 1];
#pragma unroll
        for (int c = 0; c < 4; ++c) issue_chunk(sb, h2src, c, c, tid);

        // ---- e1(t): gates1 = acc1 + bias1 + x_t*wih1 -> h1(t) ----
        frag_to_smem(G, acc1, wid, lane);
        __syncthreads();
        {
            int row = tid & 127, up = tid >> 7;
            float xv = g_xT[t * BB + row];
            union { uint32_t u; __half h[2]; } ph;
#pragma unroll
            for (int q = 0; q < 2; ++q) {
                int uu = 2 * up + q;
                float gi = G[uu * 128 + row]        + bias1[uu]      + xv * wih1[uu];
                float gf = G[(4 + uu) * 128 + row]  + bias1[4 + uu]  + xv * wih1[4 + uu];
                float gg = G[(8 + uu) * 128 + row]  + bias1[8 + uu]  + xv * wih1[8 + uu];
                float go = G[(12 + uu) * 128 + row] + bias1[12 + uu] + xv * wih1[12 + uu];
                float cn = sigf(gf) * c1st[q] + sigf(gi) * tanhf_fast(gg);
                c1st[q] = cn;
                ph.h[q] = __float2half(sigf(go) * tanhf_fast(cn));
            }
            *(uint32_t*)&g_h1[(size_t)(tid & 127) * HH + cta * 4 + 2 * (tid >> 7)] = ph.u;
        }
        bar_arrive(0, t);          // h1(t) posted

        // ---- phase H2: acc2 = W2h . h2(t-1)  (hides B1 arrivals) ----
        float acc2[2][4] = {{0, 0, 0, 0}, {0, 0, 0, 0}};
#pragma unroll
        for (int q = 0; q < 2; ++q)
#pragma unroll
            for (int j = 0; j < 4; ++j) acc1[q][j] = 0.0f;   // reset for dual pass
#pragma unroll
        for (int c = 0; c < 4; ++c) {
            if (c == 0) asm volatile("cp.async.wait_group 3;");
            if (c == 1) asm volatile("cp.async.wait_group 2;");
            if (c == 2) asm volatile("cp.async.wait_group 1;");
            if (c == 3) asm volatile("cp.async.wait_group 0;");
            __syncthreads();
            compute_chunk(sb, c, c, W2HO, acc2, wid, lane);
        }

        bar_wait(0, t);            // h1(t) visible (arrivals aged behind H2)

        // ---- phase H1: dual GEMM over h1(t) chunks ----
#pragma unroll
        for (int c = 0; c < 4; ++c) issue_chunk(sb, g_h1, c, c, tid);
#pragma unroll
        for (int c = 0; c < 4; ++c) {
            if (c == 0) asm volatile("cp.async.wait_group 3;");
            if (c == 1) asm volatile("cp.async.wait_group 2;");
            if (c == 2) asm volatile("cp.async.wait_group 1;");
            if (c == 3) asm volatile("cp.async.wait_group 0;");
            __syncthreads();
            compute_chunk_dual(sb, c, c, W2IO, acc2, W1O, acc1, wid, lane);
        }

        // ---- e2(t): gates2 -> h2(t), h2all ----
        frag_to_smem(G, acc2, wid, lane);
        __syncthreads();
        {
            int row = tid & 127, up = tid >> 7;
            union { uint32_t u; __half h[2]; } ph;
#pragma unroll
            for (int q = 0; q < 2; ++q) {
                int uu = 2 * up + q;
                float gi = G[uu * 128 + row]        + bias2[uu];
                float gf = G[(4 + uu) * 128 + row]  + bias2[4 + uu];
                float gg = G[(8 + uu) * 128 + row]  + bias2[8 + uu];
                float go = G[(12 + uu) * 128 + row] + bias2[12 + uu];
                float cn = sigf(gf) * c2st[q] + sigf(gi) * tanhf_fast(gg);
                c2st[q] = cn;
                float h = sigf(go) * tanhf_fast(cn);
                ph.h[q] = __float2half(h);
                g_h2all[(size_t)t * (HH * BB) + (cta * 4 + uu) * BB + row] = h;
            }
            *(uint32_t*)&g_h2[t & 1][(size_t)row * HH + cta * 4 + 2 * up] = ph.u;
        }
        bar_arrive(1, t);          // h2(t) posted
    }
}

// ---------------------------------------------------------------------------
// Final phase: logits = h2_all @ W_lin^T + b_lin, softmax over V (unchanged)
// ---------------------------------------------------------------------------
__global__ void __launch_bounds__(NTHR)
lin_softmax(const float* __restrict__ blin, float* __restrict__ out) {
    __shared__ float w_s[32 * VV];
    const int bx = blockIdx.x;
    const int t  = bx >> 2;
    const int bbk = bx & 3;
    const int tid = threadIdx.x;
    const int tb = tid >> 5;
    const int tc = tid & 31;

    float acc[4][8];
#pragma unroll
    for (int i = 0; i < 4; ++i)
#pragma unroll
        for (int j = 0; j < 8; ++j) acc[i][j] = 0.0f;

    for (int k0 = 0; k0 < HH; k0 += 32) {
        __syncthreads();
        for (int i = tid; i < 32 * VV; i += NTHR)
            w_s[i] = g_WlinT[k0 * VV + i];
        __syncthreads();
#pragma unroll 8
        for (int kk = 0; kk < 32; ++kk) {
            float4 hv = *(const float4*)&g_h2all[(size_t)t * (HH * BB) +
                                                 (k0 + kk) * BB + bbk * 32 + tb * 4];
            float4 w0 = *(const float4*)&w_s[kk * VV + tc * 8];
            float4 w1 = *(const float4*)&w_s[kk * VV + tc * 8 + 4];
            float hb[4] = {hv.x, hv.y, hv.z, hv.w};
            float wc[8] = {w0.x, w0.y, w0.z, w0.w, w1.x, w1.y, w1.z, w1.w};
#pragma unroll
            for (int bi = 0; bi < 4; ++bi)
#pragma unroll
                for (int vj = 0; vj < 8; ++vj)
                    acc[bi][vj] = fmaf(hb[bi], wc[vj], acc[bi][vj]);
        }
    }

    float lb[8];
    *(float4*)&lb[0] = *(const float4*)&blin[tc * 8];
    *(float4*)&lb[4] = *(const float4*)&blin[tc * 8 + 4];

#pragma unroll
    for (int bi = 0; bi < 4; ++bi) {
        float m = -1e30f;
#pragma unroll
        for (int vj = 0; vj < 8; ++vj) {
            acc[bi][vj] += lb[vj];
            m = fmaxf(m, acc[bi][vj]);
        }
#pragma unroll
        for (int off = 16; off >= 1; off >>= 1)
            m = fmaxf(m, __shfl_xor_sync(0xffffffffu, m, off));
        float s = 0.0f;
#pragma unroll
        for (int vj = 0; vj < 8; ++vj) {
            float e = expf(acc[bi][vj] - m);
            acc[bi][vj] = e;
            s += e;
        }
#pragma unroll
        for (int off = 16; off >= 1; off >>= 1)
            s += __shfl_xor_sync(0xffffffffu, s, off);
        float inv = 1.0f / s;
        size_t b = (size_t)(bbk * 32 + tb * 4 + bi);
        float4 o0 = make_float4(acc[bi][0] * inv, acc[bi][1] * inv,
                                acc[bi][2] * inv, acc[bi][3] * inv);
        float4 o1 = make_float4(acc[bi][4] * inv, acc[bi][5] * inv,
                                acc[bi][6] * inv, acc[bi][7] * inv);
        float* op = out + b * ((size_t)TT * VV) + (size_t)t * VV + tc * 8;
        *(float4*)op       = o0;
        *(float4*)(op + 4) = o1;
    }
}

// ---------------------------------------------------------------------------
extern "C" void kernel_launch(void* const* d_in, const int* in_sizes, int n_in,
                              void* d_out, int out_size) {
    const float* x    = (const float*)d_in[0];
    const float* Wih1 = (const float*)d_in[1];
    const float* Whh1 = (const float*)d_in[2];
    const float* bih1 = (const float*)d_in[3];
    const float* bhh1 = (const float*)d_in[4];
    const float* Wih2 = (const float*)d_in[5];
    const float* Whh2 = (const float*)d_in[6];
    const float* bih2 = (const float*)d_in[7];
    const float* bhh2 = (const float*)d_in[8];
    const float* Wlin = (const float*)d_in[9];
    const float* blin = (const float*)d_in[10];

    cudaFuncSetAttribute(lstm_persist, cudaFuncAttributeMaxDynamicSharedMemorySize,
                         SMEM_TOTAL);

    lstm_persist<<<NCTA, NTHR, SMEM_TOTAL>>>(x, Wih1, Whh1, bih1, bhh1,
                                             Wih2, Whh2, bih2, bhh2, Wlin);
    lin_softmax<<<TT * 4, NTHR>>>(blin, (float*)d_out);
}

// round 8
// speedup vs baseline: 4.0861x; 1.1481x over previous
#include <cuda_runtime.h>
#include <cuda_fp16.h>
#include <cstdint>

#define BB   128
#define TT   1024
#define HH   512
#define VV   256
#define NCTA 128
#define NTHR 256

// ---------------------------------------------------------------------------
// Device scratch (allocation-free).
// Chunk format: per 128x128 fp16 tile: row*256B rows, 16B-unit u stored at
// position (u ^ (row & 15))  — identical to the SMEM slot layout, so global
// <-> SMEM staging is a LINEAR 32KB copy.
// ---------------------------------------------------------------------------
__device__ __half g_h1c[4 * 16384];                      // h1(t), 4 chunks
__device__ __half g_h2all16[(size_t)TT * 4 * 16384];     // h2(t) for all t
__device__ __half g_Wlin16[VV * HH];                     // [v][k], row-XOR swz
__device__ float  g_xT[TT * BB];                         // x transposed [t][b]
__device__ unsigned g_barcnt, g_bargen;                  // init barrier
__device__ unsigned g_cnt[2], g_gen[2];                  // split-phase barriers

// ---------------------------------------------------------------------------
// Persistent-kernel SMEM: 5 A-slots (32KB) + 3 W (16KB) + G (8KB) + misc
// ---------------------------------------------------------------------------
#define SLOT(c)   ((c) * 32768)
#define W1O       163840
#define W2HO      (W1O + 16384)
#define W2IO      (W1O + 32768)
#define GOFF      (W1O + 49152)
#define MISC      (GOFF + 8192)
#define SMEM_TOTAL (MISC + 256)

// lin kernel SMEM: A ping-pong 2x32KB, B ping-pong 2x64KB, bias 1KB
#define LA0 0
#define LA1 32768
#define LB0 65536
#define LB1 131072
#define LBL 196608
#define LIN_SMEM (LBL + 1024)

__device__ __forceinline__ uint32_t smem_u32(const void* p) {
    uint32_t a;
    asm("{ .reg .u64 t; cvta.to.shared.u64 t, %1; cvt.u32.u64 %0, t; }"
        : "=r"(a) : "l"(p));
    return a;
}
__device__ __forceinline__ float sigf(float x) {
    return __fdividef(1.0f, 1.0f + __expf(-x));
}
__device__ __forceinline__ float tanhf_fast(float x) {
    return 1.0f - __fdividef(2.0f, __expf(2.0f * x) + 1.0f);
}

// ---------------------------------------------------------------------------
// Barriers (proven R3-R7)
// ---------------------------------------------------------------------------
__device__ __forceinline__ void grid_barrier() {
    __threadfence();
    __syncthreads();
    if (threadIdx.x == 0) {
        unsigned gen = *(volatile unsigned*)&g_bargen;
        unsigned arrived = atomicAdd(&g_barcnt, 1u);
        if (arrived == NCTA - 1) {
            *(volatile unsigned*)&g_barcnt = 0u;
            __threadfence();
            atomicAdd(&g_bargen, 1u);
        } else {
            while (*(volatile unsigned*)&g_bargen == gen) { }
        }
    }
    __syncthreads();
    __threadfence();
}
__device__ __forceinline__ void bar_arrive(int i, unsigned round) {
    __threadfence();
    __syncthreads();
    if (threadIdx.x == 0) {
        unsigned a = atomicAdd(&g_cnt[i], 1u);
        if (a == round * NCTA + (NCTA - 1)) {
            __threadfence();
            atomicExch(&g_gen[i], round + 1u);
        }
    }
}
__device__ __forceinline__ void bar_wait(int i, unsigned round) {
    if (threadIdx.x == 0) {
        while (*(volatile unsigned*)&g_gen[i] < round + 1u) { }
    }
    __syncthreads();
    __threadfence();
}

// ---------------------------------------------------------------------------
// Primitives
// ---------------------------------------------------------------------------
__device__ __forceinline__ void cpa16(uint32_t dst, const void* src) {
    asm volatile("cp.async.cg.shared.global [%0], [%1], 16;" :: "r"(dst), "l"(src));
}
__device__ __forceinline__ void ldm4(uint32_t a[4], uint32_t addr) {
    asm volatile("ldmatrix.sync.aligned.m8n8.x4.shared.b16 {%0,%1,%2,%3}, [%4];"
                 : "=r"(a[0]), "=r"(a[1]), "=r"(a[2]), "=r"(a[3]) : "r"(addr));
}
__device__ __forceinline__ void mma16816(float d[4], const uint32_t a[4],
                                         const uint32_t b0, const uint32_t b1) {
    asm volatile(
        "mma.sync.aligned.m16n8k16.row.col.f32.f16.f16.f32 "
        "{%0,%1,%2,%3}, {%4,%5,%6,%7}, {%8,%9}, {%0,%1,%2,%3};"
        : "+f"(d[0]), "+f"(d[1]), "+f"(d[2]), "+f"(d[3])
        : "r"(a[0]), "r"(a[1]), "r"(a[2]), "r"(a[3]), "r"(b0), "r"(b1));
}

// Linear 32KB chunk stage: global chunk (already slot-formatted) -> slot
__device__ __forceinline__ void issue_lin(uint32_t sb, int slot,
                                          const __half* __restrict__ src, int tid) {
    uint32_t base = sb + SLOT(slot);
#pragma unroll
    for (int i = 0; i < 8; ++i) {
        uint32_t off = (uint32_t)(i * NTHR + tid) * 16u;
        cpa16(base + off, (const char*)src + off);
    }
    asm volatile("cp.async.commit_group;");
}

// Single / dual GEMM chunk (addressing proven R5-R7)
__device__ __forceinline__ void compute_chunk(uint32_t sb, int slot, int kc,
                                              uint32_t wOff, float acc[2][4],
                                              int wid, int lane) {
    uint32_t arow = sb + SLOT(slot) + (wid * 16 + (lane & 15)) * 256;
    int Ra = lane & 15;
    int nn = (lane & 7) + ((lane >> 4) << 3);
    int n7 = lane & 7;
#pragma unroll
    for (int kk = 0; kk < 8; ++kk) {
        uint32_t a[4];
        int ua = kk * 2 + (lane >> 4);
        ldm4(a, arow + ((uint32_t)(ua ^ Ra) << 4));
        uint32_t b[4];
        int ug = (kc * 8 + kk) * 2 + ((lane >> 3) & 1);
        ldm4(b, sb + wOff + (uint32_t)(nn * 1024 + ((ug ^ n7) << 4)));
        mma16816(acc[0], a, b[0], b[1]);
        mma16816(acc[1], a, b[2], b[3]);
    }
}
__device__ __forceinline__ void compute_chunk_dual(uint32_t sb, int slot, int kc,
                                                   uint32_t wA, float accA[2][4],
                                                   uint32_t wB, float accB[2][4],
                                                   int wid, int lane) {
    uint32_t arow = sb + SLOT(slot) + (wid * 16 + (lane & 15)) * 256;
    int Ra = lane & 15;
    int nn = (lane & 7) + ((lane >> 4) << 3);
    int n7 = lane & 7;
#pragma unroll
    for (int kk = 0; kk < 8; ++kk) {
        uint32_t a[4];
        int ua = kk * 2 + (lane >> 4);
        ldm4(a, arow + ((uint32_t)(ua ^ Ra) << 4));
        int ug = (kc * 8 + kk) * 2 + ((lane >> 3) & 1);
        uint32_t boff = (uint32_t)(nn * 1024 + ((ug ^ n7) << 4));
        uint32_t b[4], b2[4];
        ldm4(b,  sb + wA + boff);
        ldm4(b2, sb + wB + boff);
        mma16816(accA[0], a, b[0], b[1]);
        mma16816(accA[1], a, b[2], b[3]);
        mma16816(accB[0], a, b2[0], b2[1]);
        mma16816(accB[1], a, b2[2], b2[3]);
    }
}
__device__ __forceinline__ void frag_to_smem(float* G, const float acc[2][4],
                                             int wid, int lane) {
    int r = wid * 16 + (lane >> 2);
#pragma unroll
    for (int nt = 0; nt < 2; ++nt) {
        int col = nt * 8 + 2 * (lane & 3);
        G[col * 128 + r]           = acc[nt][0];
        G[(col + 1) * 128 + r]     = acc[nt][1];
        G[col * 128 + r + 8]       = acc[nt][2];
        G[(col + 1) * 128 + r + 8] = acc[nt][3];
    }
}

// ---------------------------------------------------------------------------
// Persistent HMMA LSTM. CTA c owns hidden units [4c,4c+4) for both layers.
// ---------------------------------------------------------------------------
__global__ void __launch_bounds__(NTHR, 1)
lstm_persist(const float* __restrict__ x,
             const float* __restrict__ Wih1, const float* __restrict__ Whh1,
             const float* __restrict__ bih1, const float* __restrict__ bhh1,
             const float* __restrict__ Wih2, const float* __restrict__ Whh2,
             const float* __restrict__ bih2, const float* __restrict__ bhh2,
             const float* __restrict__ Wlin) {
    extern __shared__ char smem[];
    const uint32_t sb = smem_u32(smem);
    const int cta = blockIdx.x;
    const int tid = threadIdx.x;
    const int wid = tid >> 5;
    const int lane = tid & 31;

    float* G     = (float*)(smem + GOFF);
    float* bias1 = (float*)(smem + MISC);
    float* wih1  = (float*)(smem + MISC + 64);
    float* bias2 = (float*)(smem + MISC + 128);

    // ---- Prologue: recurrent weights -> SMEM fp16 [n][k], XOR-16B swizzle ----
    for (int m = 0; m < 3; ++m) {
        const float* W = (m == 0) ? Whh1 : (m == 1) ? Whh2 : Wih2;
        uint32_t wO = W1O + m * 16384u;
        for (int q = tid; q < 8192; q += NTHR) {
            int n = q >> 9, k = q & 511;
            int R = (n >> 2) * HH + cta * 4 + (n & 3);
            uint32_t off = (uint32_t)(n * 1024 + (((k >> 3) ^ (n & 7)) << 4) +
                                      (k & 7) * 2);
            *(__half*)(smem + wO + off) = __float2half(W[R * HH + k]);
        }
    }
    if (tid < 16) {
        int n = tid;
        int R = (n >> 2) * HH + cta * 4 + (n & 3);
        bias1[n] = bih1[R] + bhh1[R];
        wih1[n]  = Wih1[R];
        bias2[n] = bih2[R] + bhh2[R];
    }

    // ---- Global init: x transpose, W_lin -> fp16 swizzled ----
    const int gtid = cta * NTHR + tid;
    const int gstr = NCTA * NTHR;
    for (int i = gtid; i < TT * BB; i += gstr) {
        int t = i >> 7, b = i & (BB - 1);
        g_xT[i] = x[b * TT + t];
    }
    for (int i = gtid; i < VV * HH; i += gstr) {
        int v = i >> 9, k = i & 511;
        g_Wlin16[v * HH + (((k >> 3) ^ (v & 7)) << 3) + (k & 7)] =
            __float2half(Wlin[v * HH + k]);
    }
    // zero slots 0..3 (t=0 reads zeros for h2(-1))
    for (int i = tid; i < 32768; i += NTHR) ((uint32_t*)smem)[i] = 0u;
    __syncthreads();
    grid_barrier();
    if (cta == 0 && tid == 0) {
        g_cnt[0] = 0u; g_cnt[1] = 0u; g_gen[0] = 0u; g_gen[1] = 0u;
    }
    grid_barrier();

    // ---- Time loop ----
    float c1st[2] = {0, 0}, c2st[2] = {0, 0};
    float acc1[2][4] = {{0, 0, 0, 0}, {0, 0, 0, 0}};
    // per-thread write index (chunk-format) for e1/e2
    const int erow = tid & 127, eup = tid >> 7;
    const int ek  = (cta * 4 + 2 * eup) & 127;
    const uint32_t eoff =
        (uint32_t)((cta >> 5) * 16384 + erow * 128 +
                   ((((ek >> 3) ^ (erow & 15)) << 3) + (ek & 7)));  // in halves

    for (unsigned t = 0; t < TT; ++t) {
        if (t > 0) {
            bar_wait(1, t - 1);
            const __half* h2src = g_h2all16 + (size_t)(t - 1) * 65536;
            issue_lin(sb, 0, h2src,         tid);
            issue_lin(sb, 1, h2src + 16384, tid);
            issue_lin(sb, 2, h2src + 32768, tid);
            issue_lin(sb, 3, h2src + 49152, tid);
        }

        // ---- e1(t): gates1 = acc1 + bias1 + x_t*wih1 -> h1(t) chunk-format ----
        frag_to_smem(G, acc1, wid, lane);
        __syncthreads();
        {
            float xv = g_xT[t * BB + erow];
            union { uint32_t u; __half h[2]; } ph;
#pragma unroll
            for (int q = 0; q < 2; ++q) {
                int uu = 2 * eup + q;
                float gi = G[uu * 128 + erow]        + bias1[uu]      + xv * wih1[uu];
                float gf = G[(4 + uu) * 128 + erow]  + bias1[4 + uu]  + xv * wih1[4 + uu];
                float gg = G[(8 + uu) * 128 + erow]  + bias1[8 + uu]  + xv * wih1[8 + uu];
                float go = G[(12 + uu) * 128 + erow] + bias1[12 + uu] + xv * wih1[12 + uu];
                float cn = sigf(gf) * c1st[q] + sigf(gi) * tanhf_fast(gg);
                c1st[q] = cn;
                ph.h[q] = __float2half(sigf(go) * tanhf_fast(cn));
            }
            *(uint32_t*)&g_h1c[eoff] = ph.u;
        }
        bar_arrive(0, t);

        float acc2[2][4] = {{0, 0, 0, 0}, {0, 0, 0, 0}};
#pragma unroll
        for (int q = 0; q < 2; ++q)
#pragma unroll
            for (int j = 0; j < 4; ++j) acc1[q][j] = 0.0f;

        // ---- H2 phase with interleaved h1 prefetch (5-slot schedule) ----
        asm volatile("cp.async.wait_group 3;");
        __syncthreads();
        compute_chunk(sb, 0, 0, W2HO, acc2, wid, lane);

        asm volatile("cp.async.wait_group 2;");
        __syncthreads();
        compute_chunk(sb, 1, 1, W2HO, acc2, wid, lane);

        bar_wait(0, t);                       // h1(t) visible (aged 2 chunks)
        issue_lin(sb, 4, g_h1c,         tid); // h1 c0 -> slot4

        asm volatile("cp.async.wait_group 2;");
        __syncthreads();
        compute_chunk(sb, 2, 2, W2HO, acc2, wid, lane);
        issue_lin(sb, 0, g_h1c + 16384, tid); // h1 c1 -> slot0 (consumed)

        asm volatile("cp.async.wait_group 2;");
        __syncthreads();
        compute_chunk(sb, 3, 3, W2HO, acc2, wid, lane);
        issue_lin(sb, 1, g_h1c + 32768, tid); // h1 c2 -> slot1

        // ---- H1 phase: dual GEMM (acc2 += W2i.h1 ; acc1 = W1.h1) ----
        asm volatile("cp.async.wait_group 2;");
        __syncthreads();
        compute_chunk_dual(sb, 4, 0, W2IO, acc2, W1O, acc1, wid, lane);
        issue_lin(sb, 2, g_h1c + 49152, tid); // h1 c3 -> slot2

        asm volatile("cp.async.wait_group 2;");
        __syncthreads();
        compute_chunk_dual(sb, 0, 1, W2IO, acc2, W1O, acc1, wid, lane);

        asm volatile("cp.async.wait_group 1;");
        __syncthreads();
        compute_chunk_dual(sb, 1, 2, W2IO, acc2, W1O, acc1, wid, lane);

        asm volatile("cp.async.wait_group 0;");
        __syncthreads();
        compute_chunk_dual(sb, 2, 3, W2IO, acc2, W1O, acc1, wid, lane);

        // ---- e2(t): gates2 -> h2(t) chunk-format ----
        frag_to_smem(G, acc2, wid, lane);
        __syncthreads();
        {
            union { uint32_t u; __half h[2]; } ph;
#pragma unroll
            for (int q = 0; q < 2; ++q) {
                int uu = 2 * eup + q;
                float gi = G[uu * 128 + erow]        + bias2[uu];
                float gf = G[(4 + uu) * 128 + erow]  + bias2[4 + uu];
                float gg = G[(8 + uu) * 128 + erow]  + bias2[8 + uu];
                float go = G[(12 + uu) * 128 + erow] + bias2[12 + uu];
                float cn = sigf(gf) * c2st[q] + sigf(gi) * tanhf_fast(gg);
                c2st[q] = cn;
                ph.h[q] = __float2half(sigf(go) * tanhf_fast(cn));
            }
            *(uint32_t*)&g_h2all16[(size_t)t * 65536 + eoff] = ph.u;
        }
        bar_arrive(1, t);
    }
}

// ---------------------------------------------------------------------------
// Final phase (HMMA): per t: logits[128,256] = h2(t) @ Wlin^T + b, softmax.
// ---------------------------------------------------------------------------
__global__ void __launch_bounds__(NTHR)
lin_hmma(const float* __restrict__ blin, float* __restrict__ out) {
    extern __shared__ char smem[];
    const uint32_t sb = smem_u32(smem);
    const int t   = blockIdx.x;
    const int tid = threadIdx.x;
    const int wid = tid >> 5;
    const int lane = tid & 31;
    float* bl_s = (float*)(smem + LBL);
    if (tid < VV) bl_s[tid] = blin[tid];

    const __half* Asrc = g_h2all16 + (size_t)t * 65536;

    // chunk staging: A linear 32KB; B 256 rows x 256B (local swizzle preserved)
    auto issue = [&](int kc, int ib) {
        uint32_t ab = sb + (ib ? LA1 : LA0);
#pragma unroll
        for (int i = 0; i < 8; ++i) {
            uint32_t off = (uint32_t)(i * NTHR + tid) * 16u;
            cpa16(ab + off, (const char*)Asrc + kc * 32768 + off);
        }
        uint32_t bb = sb + (ib ? LB1 : LB0);
#pragma unroll
        for (int i = 0; i < 16; ++i) {
            int idx = i * NTHR + tid;
            int n = idx >> 4, u = idx & 15;
            cpa16(bb + (uint32_t)(n * 256 + u * 16),
                  (const char*)g_Wlin16 + n * 1024 + kc * 256 + u * 16);
        }
        asm volatile("cp.async.commit_group;");
    };

    float acc[32][4];
#pragma unroll
    for (int nt = 0; nt < 32; ++nt)
#pragma unroll
        for (int j = 0; j < 4; ++j) acc[nt][j] = 0.0f;

    issue(0, 0);
    issue(1, 1);
    const int Ra = lane & 15;
    const int n7 = lane & 7;
    const int nbase = (lane & 7) + ((lane >> 4) << 3);
    const int ugb = (lane >> 3) & 1;

    for (int kc = 0; kc < 4; ++kc) {
        if (kc < 3) asm volatile("cp.async.wait_group 1;");
        else        asm volatile("cp.async.wait_group 0;");
        __syncthreads();
        uint32_t ab = sb + ((kc & 1) ? LA1 : LA0);
        uint32_t bb = sb + ((kc & 1) ? LB1 : LB0);
        uint32_t arow = ab + (wid * 16 + (lane & 15)) * 256;
#pragma unroll
        for (int kk = 0; kk < 8; ++kk) {
            uint32_t a[4];
            int ua = kk * 2 + (lane >> 4);
            ldm4(a, arow + ((uint32_t)(ua ^ Ra) << 4));
            int ug = kk * 2 + ugb;
            uint32_t bsw = (uint32_t)((ug ^ n7) << 4);
#pragma unroll
            for (int ntp = 0; ntp < 16; ++ntp) {
                uint32_t b[4];
                ldm4(b, bb + (uint32_t)((nbase + ntp * 16) * 256) + bsw);
                mma16816(acc[2 * ntp],     a, b[0], b[1]);
                mma16816(acc[2 * ntp + 1], a, b[2], b[3]);
            }
        }
        __syncthreads();
        if (kc < 2) issue(kc + 2, kc & 1);
    }

    // ---- bias + softmax (rows r0 = 16w + lane/4 and r0+8) ----
    const int r0 = wid * 16 + (lane >> 2);
    const int cb = 2 * (lane & 3);
    float m0 = -1e30f, m1 = -1e30f;
#pragma unroll
    for (int nt = 0; nt < 32; ++nt) {
        float b0 = bl_s[nt * 8 + cb], b1 = bl_s[nt * 8 + cb + 1];
        acc[nt][0] += b0; acc[nt][1] += b1;
        acc[nt][2] += b0; acc[nt][3] += b1;
        m0 = fmaxf(m0, fmaxf(acc[nt][0], acc[nt][1]));
        m1 = fmaxf(m1, fmaxf(acc[nt][2], acc[nt][3]));
    }
    m0 = fmaxf(m0, __shfl_xor_sync(0xffffffffu, m0, 1));
    m0 = fmaxf(m0, __shfl_xor_sync(0xffffffffu, m0, 2));
    m1 = fmaxf(m1, __shfl_xor_sync(0xffffffffu, m1, 1));
    m1 = fmaxf(m1, __shfl_xor_sync(0xffffffffu, m1, 2));
    float s0 = 0.0f, s1 = 0.0f;
#pragma unroll
    for (int nt = 0; nt < 32; ++nt) {
        acc[nt][0] = __expf(acc[nt][0] - m0); s0 += acc[nt][0];
        acc[nt][1] = __expf(acc[nt][1] - m0); s0 += acc[nt][1];
        acc[nt][2] = __expf(acc[nt][2] - m1); s1 += acc[nt][2];
        acc[nt][3] = __expf(acc[nt][3] - m1); s1 += acc[nt][3];
    }
    s0 += __shfl_xor_sync(0xffffffffu, s0, 1);
    s0 += __shfl_xor_sync(0xffffffffu, s0, 2);
    s1 += __shfl_xor_sync(0xffffffffu, s1, 1);
    s1 += __shfl_xor_sync(0xffffffffu, s1, 2);
    float inv0 = __fdividef(1.0f, s0);
    float inv1 = __fdividef(1.0f, s1);
    float* o0 = out + ((size_t)r0 * TT + t) * VV;
    float* o1 = out + ((size_t)(r0 + 8) * TT + t) * VV;
#pragma unroll
    for (int nt = 0; nt < 32; ++nt) {
        int c = nt * 8 + cb;
        *(float2*)(o0 + c) = make_float2(acc[nt][0] * inv0, acc[nt][1] * inv0);
        *(float2*)(o1 + c) = make_float2(acc[nt][2] * inv1, acc[nt][3] * inv1);
    }
}

// ---------------------------------------------------------------------------
extern "C" void kernel_launch(void* const* d_in, const int* in_sizes, int n_in,
                              void* d_out, int out_size) {
    const float* x    = (const float*)d_in[0];
    const float* Wih1 = (const float*)d_in[1];
    const float* Whh1 = (const float*)d_in[2];
    const float* bih1 = (const float*)d_in[3];
    const float* bhh1 = (const float*)d_in[4];
    const float* Wih2 = (const float*)d_in[5];
    const float* Whh2 = (const float*)d_in[6];
    const float* bih2 = (const float*)d_in[7];
    const float* bhh2 = (const float*)d_in[8];
    const float* Wlin = (const float*)d_in[9];
    const float* blin = (const float*)d_in[10];

    cudaFuncSetAttribute(lstm_persist, cudaFuncAttributeMaxDynamicSharedMemorySize,
                         SMEM_TOTAL);
    cudaFuncSetAttribute(lin_hmma, cudaFuncAttributeMaxDynamicSharedMemorySize,
                         LIN_SMEM);

    lstm_persist<<<NCTA, NTHR, SMEM_TOTAL>>>(x, Wih1, Whh1, bih1, bhh1,
                                             Wih2, Whh2, bih2, bhh2, Wlin);
    lin_hmma<<<TT, NTHR, LIN_SMEM>>>(blin, (float*)d_out);
}

// round 12
// speedup vs baseline: 4.3133x; 1.0556x over previous
#include <cuda_runtime.h>
#include <cuda_fp16.h>
#include <cstdint>

#define BB   128
#define TT   1024
#define HH   512
#define VV   256
#define NCTA 128      // total CTAs = 2 groups x 64
#define NCG  64       // CTAs per group
#define NTHR 256

// ---------------------------------------------------------------------------
// Device scratch (allocation-free).
// Chunk format (per 64x128 fp16 tile = 8192 halves = 16 KB): row*256B rows,
// 16B-unit u stored at (u ^ (row & 15)) — identical to SMEM slot layout, so
// global <-> SMEM staging is a LINEAR 16 KB copy.
// h layouts: g_h1c[g][kc][8192]; g_h2all16[t][g][kc][8192].
// ---------------------------------------------------------------------------
__device__ __half g_h1c[2 * 4 * 8192];
__device__ __half g_h2all16[(size_t)TT * 65536];
__device__ __half g_Wlin16[VV * HH];                 // [v][k], row-XOR swz
__device__ float  g_xT[TT * BB];                     // x transposed [t][b]
__device__ unsigned g_barcnt, g_bargen;              // global init barrier
__device__ unsigned g_cnt[4], g_gen[4];              // per-group split barriers

// ---------------------------------------------------------------------------
// Persistent SMEM: 5 slots x 16KB + 3 W x 32KB + G 8KB + misc
// ---------------------------------------------------------------------------
#define SLOT(c)   ((c) * 16384)
#define W1O       81920
#define W2HO      (W1O + 32768)
#define W2IO      (W1O + 65536)
#define GOFF      (W1O + 98304)
#define MISC      (GOFF + 8192)
#define SMEM_TOTAL (MISC + 512)

// lin kernel SMEM
#define LA0 0
#define LA1 32768
#define LB0 65536
#define LB1 131072
#define LBL 196608
#define LIN_SMEM (LBL + 1024)

__device__ __forceinline__ uint32_t smem_u32(const void* p) {
    uint32_t a;
    asm("{ .reg .u64 t; cvta.to.shared.u64 t, %1; cvt.u32.u64 %0, t; }"
        : "=r"(a) : "l"(p));
    return a;
}
__device__ __forceinline__ float sigf(float x) {
    return __fdividef(1.0f, 1.0f + __expf(-x));
}
__device__ __forceinline__ float tanhf_fast(float x) {
    return 1.0f - __fdividef(2.0f, __expf(2.0f * x) + 1.0f);
}

// ---------------------------------------------------------------------------
// Global init barrier (128 CTAs) + per-group split-phase barriers (64 CTAs)
// ---------------------------------------------------------------------------
__device__ __forceinline__ void grid_barrier() {
    __threadfence();
    __syncthreads();
    if (threadIdx.x == 0) {
        unsigned gen = *(volatile unsigned*)&g_bargen;
        unsigned arrived = atomicAdd(&g_barcnt, 1u);
        if (arrived == NCTA - 1) {
            *(volatile unsigned*)&g_barcnt = 0u;
            __threadfence();
            atomicAdd(&g_bargen, 1u);
        } else {
            while (*(volatile unsigned*)&g_bargen == gen) { }
        }
    }
    __syncthreads();
    __threadfence();
}
__device__ __forceinline__ void bar_arrive(int idx, unsigned round) {
    __threadfence();
    __syncthreads();
    if (threadIdx.x == 0) {
        unsigned a = atomicAdd(&g_cnt[idx], 1u);
        if (a == round * NCG + (NCG - 1)) {
            __threadfence();
            atomicExch(&g_gen[idx], round + 1u);
        }
    }
}
__device__ __forceinline__ void bar_wait(int idx, unsigned round) {
    if (threadIdx.x == 0) {
        while (*(volatile unsigned*)&g_gen[idx] < round + 1u) { }
    }
    __syncthreads();
    __threadfence();
}

// ---------------------------------------------------------------------------
// Primitives
// ---------------------------------------------------------------------------
__device__ __forceinline__ void cpa16(uint32_t dst, const void* src) {
    asm volatile("cp.async.cg.shared.global [%0], [%1], 16;" :: "r"(dst), "l"(src));
}
__device__ __forceinline__ void ldm4(uint32_t a[4], uint32_t addr) {
    asm volatile("ldmatrix.sync.aligned.m8n8.x4.shared.b16 {%0,%1,%2,%3}, [%4];"
                 : "=r"(a[0]), "=r"(a[1]), "=r"(a[2]), "=r"(a[3]) : "r"(addr));
}
__device__ __forceinline__ void mma16816(float d[4], const uint32_t a[4],
                                         const uint32_t b0, const uint32_t b1) {
    asm volatile(
        "mma.sync.aligned.m16n8k16.row.col.f32.f16.f16.f32 "
        "{%0,%1,%2,%3}, {%4,%5,%6,%7}, {%8,%9}, {%0,%1,%2,%3};"
        : "+f"(d[0]), "+f"(d[1]), "+f"(d[2]), "+f"(d[3])
        : "r"(a[0]), "r"(a[1]), "r"(a[2]), "r"(a[3]), "r"(b0), "r"(b1));
}

// Linear 16KB chunk stage: slot-formatted global chunk -> slot
__device__ __forceinline__ void issue_lin(uint32_t sb, int slot,
                                          const __half* __restrict__ src, int tid) {
    uint32_t base = sb + SLOT(slot);
#pragma unroll
    for (int i = 0; i < 4; ++i) {
        uint32_t off = (uint32_t)(i * NTHR + tid) * 16u;
        cpa16(base + off, (const char*)src + off);
    }
    asm volatile("cp.async.commit_group;");
}

// M=64 x N=32 tile; warp (mw = wid&3, nw = wid>>2): rows 16mw.., cols 16nw..
__device__ __forceinline__ void compute_chunk(uint32_t sb, int slot, int kc,
                                              uint32_t wOff, float acc[2][4],
                                              int mw, int nw, int lane) {
    uint32_t arow = sb + SLOT(slot) + (mw * 16 + (lane & 15)) * 256;
    int Ra = lane & 15;
    int nn = nw * 16 + (lane & 7) + ((lane >> 4) << 3);
    int n7 = lane & 7;
#pragma unroll
    for (int kk = 0; kk < 8; ++kk) {
        uint32_t a[4];
        int ua = kk * 2 + (lane >> 4);
        ldm4(a, arow + ((uint32_t)(ua ^ Ra) << 4));
        uint32_t b[4];
        int ug = (kc * 8 + kk) * 2 + ((lane >> 3) & 1);
        ldm4(b, sb + wOff + (uint32_t)(nn * 1024 + ((ug ^ n7) << 4)));
        mma16816(acc[0], a, b[0], b[1]);
        mma16816(acc[1], a, b[2], b[3]);
    }
}
__device__ __forceinline__ void compute_chunk_dual(uint32_t sb, int slot, int kc,
                                                   uint32_t wA, float accA[2][4],
                                                   uint32_t wB, float accB[2][4],
                                                   int mw, int nw, int lane) {
    uint32_t arow = sb + SLOT(slot) + (mw * 16 + (lane & 15)) * 256;
    int Ra = lane & 15;
    int nn = nw * 16 + (lane & 7) + ((lane >> 4) << 3);
    int n7 = lane & 7;
#pragma unroll
    for (int kk = 0; kk < 8; ++kk) {
        uint32_t a[4];
        int ua = kk * 2 + (lane >> 4);
        ldm4(a, arow + ((uint32_t)(ua ^ Ra) << 4));
        int ug = (kc * 8 + kk) * 2 + ((lane >> 3) & 1);
        uint32_t boff = (uint32_t)(nn * 1024 + ((ug ^ n7) << 4));
        uint32_t b[4], b2[4];
        ldm4(b,  sb + wA + boff);
        ldm4(b2, sb + wB + boff);
        mma16816(accA[0], a, b[0], b[1]);
        mma16816(accA[1], a, b[2], b[3]);
        mma16816(accB[0], a, b2[0], b2[1]);
        mma16816(accB[1], a, b2[2], b2[3]);
    }
}
// G[col][row]: 32 cols x 64 rows f32
__device__ __forceinline__ void frag_to_smem(float* G, const float acc[2][4],
                                             int mw, int nw, int lane) {
    int r = mw * 16 + (lane >> 2);
#pragma unroll
    for (int nt = 0; nt < 2; ++nt) {
        int col = nw * 16 + nt * 8 + 2 * (lane & 3);
        G[col * 64 + r]           = acc[nt][0];
        G[(col + 1) * 64 + r]     = acc[nt][1];
        G[col * 64 + r + 8]       = acc[nt][2];
        G[(col + 1) * 64 + r + 8] = acc[nt][3];
    }
}

// ---------------------------------------------------------------------------
// Persistent HMMA LSTM, 2 independent batch groups.
// Group g = cta>>6 (batch rows [64g,64g+64)); cl = cta&63 owns hidden units
// [8cl, 8cl+8) for both layers (N=32 gate cols, gate-interleaved col=gate*8+u).
// ---------------------------------------------------------------------------
__global__ void __launch_bounds__(NTHR, 1)
lstm_persist(const float* __restrict__ x,
             const float* __restrict__ Wih1, const float* __restrict__ Whh1,
             const float* __restrict__ bih1, const float* __restrict__ bhh1,
             const float* __restrict__ Wih2, const float* __restrict__ Whh2,
             const float* __restrict__ bih2, const float* __restrict__ bhh2,
             const float* __restrict__ Wlin) {
    extern __shared__ char smem[];
    const uint32_t sb = smem_u32(smem);
    const int cta = blockIdx.x;
    const int grp = cta >> 6;
    const int cl  = cta & 63;
    const int tid = threadIdx.x;
    const int wid = tid >> 5;
    const int lane = tid & 31;
    const int mw = wid & 3, nw = wid >> 2;

    float* G     = (float*)(smem + GOFF);
    float* bias1 = (float*)(smem + MISC);
    float* wih1  = (float*)(smem + MISC + 128);
    float* bias2 = (float*)(smem + MISC + 256);

    // ---- Prologue: recurrent weights -> SMEM fp16 [n=32][k=512], XOR swz ----
    for (int m = 0; m < 3; ++m) {
        const float* W = (m == 0) ? Whh1 : (m == 1) ? Whh2 : Wih2;
        uint32_t wO = W1O + m * 32768u;
        for (int q = tid; q < 16384; q += NTHR) {
            int n = q >> 9, k = q & 511;
            int R = (n >> 3) * HH + cl * 8 + (n & 7);
            uint32_t off = (uint32_t)(n * 1024 + (((k >> 3) ^ (n & 7)) << 4) +
                                      (k & 7) * 2);
            *(__half*)(smem + wO + off) = __float2half(W[R * HH + k]);
        }
    }
    if (tid < 32) {
        int n = tid;
        int R = (n >> 3) * HH + cl * 8 + (n & 7);
        bias1[n] = bih1[R] + bhh1[R];
        wih1[n]  = Wih1[R];
        bias2[n] = bih2[R] + bhh2[R];
    }

    // ---- Global init: x transpose, W_lin fp16 swizzled ----
    const int gtid = cta * NTHR + tid;
    const int gstr = NCTA * NTHR;
    for (int i = gtid; i < TT * BB; i += gstr) {
        int t = i >> 7, b = i & (BB - 1);
        g_xT[i] = x[b * TT + t];
    }
    for (int i = gtid; i < VV * HH; i += gstr) {
        int v = i >> 9, k = i & 511;
        g_Wlin16[v * HH + (((k >> 3) ^ (v & 7)) << 3) + (k & 7)] =
            __float2half(Wlin[v * HH + k]);
    }
    // zero slots 0..3 (t=0 reads zeros for h2(-1))
    for (int i = tid; i < 16384; i += NTHR) ((uint32_t*)smem)[i] = 0u;
    __syncthreads();
    grid_barrier();
    if (cta == 0 && tid == 0) {
        for (int i = 0; i < 4; ++i) { g_cnt[i] = 0u; g_gen[i] = 0u; }
    }
    grid_barrier();

    // ---- Time loop ----
    const int bW = grp * 2 + 0;    // h1 barrier for this group
    const int bH = grp * 2 + 1;    // h2 barrier
    float c1st[2] = {0, 0}, c2st[2] = {0, 0};
    float acc1[2][4] = {{0, 0, 0, 0}, {0, 0, 0, 0}};
    // epilogue thread mapping: row = tid&63, unit pair up = tid>>6
    const int erow = tid & 63, eup = tid >> 6;
    const uint32_t eoff =
        (uint32_t)((cl >> 4) * 8192 + erow * 128 +
                   ((((cl & 15) ^ (erow & 15)) << 3) + 2 * eup));  // halves
    const __half* h1src = g_h1c + grp * 32768;

    for (unsigned t = 0; t < TT; ++t) {
        if (t > 0) {
            bar_wait(bH, t - 1);
            const __half* h2src = g_h2all16 + (size_t)(t - 1) * 65536 + grp * 32768;
            issue_lin(sb, 0, h2src,         tid);
            issue_lin(sb, 1, h2src + 8192,  tid);
            issue_lin(sb, 2, h2src + 16384, tid);
            issue_lin(sb, 3, h2src + 24576, tid);
        }

        // ---- e1(t): gates1 -> h1(t) chunk-format ----
        frag_to_smem(G, acc1, mw, nw, lane);
        __syncthreads();
        {
            float xv = g_xT[t * BB + grp * 64 + erow];
            union { uint32_t u; __half h[2]; } ph;
#pragma unroll
            for (int q = 0; q < 2; ++q) {
                int u = 2 * eup + q;
                float gi = G[u * 64 + erow]        + bias1[u]      + xv * wih1[u];
                float gf = G[(8 + u) * 64 + erow]  + bias1[8 + u]  + xv * wih1[8 + u];
                float gg = G[(16 + u) * 64 + erow] + bias1[16 + u] + xv * wih1[16 + u];
                float go = G[(24 + u) * 64 + erow] + bias1[24 + u] + xv * wih1[24 + u];
                float cn = sigf(gf) * c1st[q] + sigf(gi) * tanhf_fast(gg);
                c1st[q] = cn;
                ph.h[q] = __float2half(sigf(go) * tanhf_fast(cn));
            }
            *(uint32_t*)&g_h1c[grp * 32768 + eoff] = ph.u;
        }
        bar_arrive(bW, t);

        float acc2[2][4] = {{0, 0, 0, 0}, {0, 0, 0, 0}};
#pragma unroll
        for (int q = 0; q < 2; ++q)
#pragma unroll
            for (int j = 0; j < 4; ++j) acc1[q][j] = 0.0f;

        // ---- H2 phase with interleaved h1 prefetch (5-slot schedule) ----
        asm volatile("cp.async.wait_group 3;");
        __syncthreads();
        compute_chunk(sb, 0, 0, W2HO, acc2, mw, nw, lane);

        asm volatile("cp.async.wait_group 2;");
        __syncthreads();
        compute_chunk(sb, 1, 1, W2HO, acc2, mw, nw, lane);

        bar_wait(bW, t);                      // h1(t) visible (aged 2 chunks)
        issue_lin(sb, 4, h1src,         tid);

        asm volatile("cp.async.wait_group 2;");
        __syncthreads();
        compute_chunk(sb, 2, 2, W2HO, acc2, mw, nw, lane);
        issue_lin(sb, 0, h1src + 8192,  tid);

        asm volatile("cp.async.wait_group 2;");
        __syncthreads();
        compute_chunk(sb, 3, 3, W2HO, acc2, mw, nw, lane);
        issue_lin(sb, 1, h1src + 16384, tid);

        // ---- H1 phase: dual GEMM (acc2 += W2i.h1 ; acc1 = W1.h1) ----
        asm volatile("cp.async.wait_group 2;");
        __syncthreads();
        compute_chunk_dual(sb, 4, 0, W2IO, acc2, W1O, acc1, mw, nw, lane);
        issue_lin(sb, 2, h1src + 24576, tid);

        asm volatile("cp.async.wait_group 2;");
        __syncthreads();
        compute_chunk_dual(sb, 0, 1, W2IO, acc2, W1O, acc1, mw, nw, lane);

        asm volatile("cp.async.wait_group 1;");
        __syncthreads();
        compute_chunk_dual(sb, 1, 2, W2IO, acc2, W1O, acc1, mw, nw, lane);

        asm volatile("cp.async.wait_group 0;");
        __syncthreads();
        compute_chunk_dual(sb, 2, 3, W2IO, acc2, W1O, acc1, mw, nw, lane);

        // ---- e2(t): gates2 -> h2(t) chunk-format ----
        frag_to_smem(G, acc2, mw, nw, lane);
        __syncthreads();
        {
            union { uint32_t u; __half h[2]; } ph;
#pragma unroll
            for (int q = 0; q < 2; ++q) {
                int u = 2 * eup + q;
                float gi = G[u * 64 + erow]        + bias2[u];
                float gf = G[(8 + u) * 64 + erow]  + bias2[8 + u];
                float gg = G[(16 + u) * 64 + erow] + bias2[16 + u];
                float go = G[(24 + u) * 64 + erow] + bias2[24 + u];
                float cn = sigf(gf) * c2st[q] + sigf(gi) * tanhf_fast(gg);
                c2st[q] = cn;
                ph.h[q] = __float2half(sigf(go) * tanhf_fast(cn));
            }
            *(uint32_t*)&g_h2all16[(size_t)t * 65536 + grp * 32768 + eoff] = ph.u;
        }
        bar_arrive(bH, t);
    }
}

// ---------------------------------------------------------------------------
// Final phase (HMMA): per t: logits[128,256] = h2(t) @ Wlin^T + b, softmax.
// A tile: rows 0-63 = group0 chunk kc, rows 64-127 = group1 chunk kc.
// ---------------------------------------------------------------------------
__global__ void __launch_bounds__(NTHR)
lin_hmma(const float* __restrict__ blin, float* __restrict__ out) {
    extern __shared__ char smem[];
    const uint32_t sb = smem_u32(smem);
    const int t   = blockIdx.x;
    const int tid = threadIdx.x;
    const int wid = tid >> 5;
    const int lane = tid & 31;
    float* bl_s = (float*)(smem + LBL);
    if (tid < VV) bl_s[tid] = blin[tid];

    const char* Asrc = (const char*)g_h2all16 + (size_t)t * 131072;

    auto issue = [&](int kc, int ib) {
        uint32_t ab = sb + (ib ? LA1 : LA0);
#pragma unroll
        for (int i = 0; i < 8; ++i) {
            uint32_t off = (uint32_t)(i * NTHR + tid) * 16u;   // 0..32767
            uint32_t g = off >> 14, loff = off & 16383u;
            cpa16(ab + off, Asrc + g * 65536 + (uint32_t)kc * 16384 + loff);
        }
        uint32_t bb = sb + (ib ? LB1 : LB0);
#pragma unroll
        for (int i = 0; i < 16; ++i) {
            int idx = i * NTHR + tid;
            int n = idx >> 4, u = idx & 15;
            cpa16(bb + (uint32_t)(n * 256 + u * 16),
                  (const char*)g_Wlin16 + n * 1024 + kc * 256 + u * 16);
        }
        asm volatile("cp.async.commit_group;");
    };

    float acc[32][4];
#pragma unroll
    for (int nt = 0; nt < 32; ++nt)
#pragma unroll
        for (int j = 0; j < 4; ++j) acc[nt][j] = 0.0f;

    issue(0, 0);
    issue(1, 1);
    const int Ra = lane & 15;
    const int n7 = lane & 7;
    const int nbase = (lane & 7) + ((lane >> 4) << 3);
    const int ugb = (lane >> 3) & 1;

    for (int kc = 0; kc < 4; ++kc) {
        if (kc < 3) asm volatile("cp.async.wait_group 1;");
        else        asm volatile("cp.async.wait_group 0;");
        __syncthreads();
        uint32_t ab = sb + ((kc & 1) ? LA1 : LA0);
        uint32_t bb = sb + ((kc & 1) ? LB1 : LB0);
        uint32_t arow = ab + (wid * 16 + (lane & 15)) * 256;
#pragma unroll
        for (int kk = 0; kk < 8; ++kk) {
            uint32_t a[4];
            int ua = kk * 2 + (lane >> 4);
            ldm4(a, arow + ((uint32_t)(ua ^ Ra) << 4));
            int ug = kk * 2 + ugb;
            uint32_t bsw = (uint32_t)((ug ^ n7) << 4);
#pragma unroll
            for (int ntp = 0; ntp < 16; ++ntp) {
                uint32_t b[4];
                ldm4(b, bb + (uint32_t)((nbase + ntp * 16) * 256) + bsw);
                mma16816(acc[2 * ntp],     a, b[0], b[1]);
                mma16816(acc[2 * ntp + 1], a, b[2], b[3]);
            }
        }
        __syncthreads();
        if (kc < 2) issue(kc + 2, kc & 1);
    }

    // ---- bias + softmax (rows r0 and r0+8) ----
    const int r0 = wid * 16 + (lane >> 2);
    const int cb = 2 * (lane & 3);
    float m0 = -1e30f, m1 = -1e30f;
#pragma unroll
    for (int nt = 0; nt < 32; ++nt) {
        float b0 = bl_s[nt * 8 + cb], b1 = bl_s[nt * 8 + cb + 1];
        acc[nt][0] += b0; acc[nt][1] += b1;
        acc[nt][2] += b0; acc[nt][3] += b1;
        m0 = fmaxf(m0, fmaxf(acc[nt][0], acc[nt][1]));
        m1 = fmaxf(m1, fmaxf(acc[nt][2], acc[nt][3]));
    }
    m0 = fmaxf(m0, __shfl_xor_sync(0xffffffffu, m0, 1));
    m0 = fmaxf(m0, __shfl_xor_sync(0xffffffffu, m0, 2));
    m1 = fmaxf(m1, __shfl_xor_sync(0xffffffffu, m1, 1));
    m1 = fmaxf(m1, __shfl_xor_sync(0xffffffffu, m1, 2));
    float s0 = 0.0f, s1 = 0.0f;
#pragma unroll
    for (int nt = 0; nt < 32; ++nt) {
        acc[nt][0] = __expf(acc[nt][0] - m0); s0 += acc[nt][0];
        acc[nt][1] = __expf(acc[nt][1] - m0); s0 += acc[nt][1];
        acc[nt][2] = __expf(acc[nt][2] - m1); s1 += acc[nt][2];
        acc[nt][3] = __expf(acc[nt][3] - m1); s1 += acc[nt][3];
    }
    s0 += __shfl_xor_sync(0xffffffffu, s0, 1);
    s0 += __shfl_xor_sync(0xffffffffu, s0, 2);
    s1 += __shfl_xor_sync(0xffffffffu, s1, 1);
    s1 += __shfl_xor_sync(0xffffffffu, s1, 2);
    float inv0 = __fdividef(1.0f, s0);
    float inv1 = __fdividef(1.0f, s1);
    float* o0 = out + ((size_t)r0 * TT + t) * VV;
    float* o1 = out + ((size_t)(r0 + 8) * TT + t) * VV;
#pragma unroll
    for (int nt = 0; nt < 32; ++nt) {
        int c = nt * 8 + cb;
        *(float2*)(o0 + c) = make_float2(acc[nt][0] * inv0, acc[nt][1] * inv0);
        *(float2*)(o1 + c) = make_float2(acc[nt][2] * inv1, acc[nt][3] * inv1);
    }
}

// ---------------------------------------------------------------------------
extern "C" void kernel_launch(void* const* d_in, const int* in_sizes, int n_in,
                              void* d_out, int out_size) {
    const float* x    = (const float*)d_in[0];
    const float* Wih1 = (const float*)d_in[1];
    const float* Whh1 = (const float*)d_in[2];
    const float* bih1 = (const float*)d_in[3];
    const float* bhh1 = (const float*)d_in[4];
    const float* Wih2 = (const float*)d_in[5];
    const float* Whh2 = (const float*)d_in[6];
    const float* bih2 = (const float*)d_in[7];
    const float* bhh2 = (const float*)d_in[8];
    const float* Wlin = (const float*)d_in[9];
    const float* blin = (const float*)d_in[10];

    cudaFuncSetAttribute(lstm_persist, cudaFuncAttributeMaxDynamicSharedMemorySize,
                         SMEM_TOTAL);
    cudaFuncSetAttribute(lin_hmma, cudaFuncAttributeMaxDynamicSharedMemorySize,
                         LIN_SMEM);

    lstm_persist<<<NCTA, NTHR, SMEM_TOTAL>>>(x, Wih1, Whh1, bih1, bhh1,
                                             Wih2, Whh2, bih2, bhh2, Wlin);
    lin_hmma<<<TT, NTHR, LIN_SMEM>>>(blin, (float*)d_out);
}